// round 14
// baseline (speedup 1.0000x reference)
#include <cuda_runtime.h>
#include <math.h>
#include <stdint.h>

#define NB 2
#define NS 2048
#define NH 16
#define NDK 64
#define NDM 1024
#define NROWS (NB*NS)   // 4096

// Scratch (no allocs allowed)
__device__ float g_Q[(size_t)NROWS*NDM];   // d-permuted per head slice, tf32-rounded
__device__ float g_K[(size_t)NROWS*NDK];   // d-permuted, tf32-rounded
__device__ float g_V[(size_t)NROWS*NDK];   // canonical, tf32-rounded
__device__ float g_X[(size_t)NROWS*NDM];   // canonical
__device__ float g_L[NB*NH*NS];

// ===========================================================================
// helpers
// ===========================================================================
__device__ __forceinline__ void mma_tf32(float (&d)[4], const uint32_t (&a)[4],
                                         const uint32_t (&b)[2]) {
    asm volatile("mma.sync.aligned.m16n8k8.row.col.f32.tf32.tf32.f32 "
        "{%0,%1,%2,%3}, {%4,%5,%6,%7}, {%8,%9}, {%0,%1,%2,%3};"
        : "+f"(d[0]), "+f"(d[1]), "+f"(d[2]), "+f"(d[3])
        : "r"(a[0]), "r"(a[1]), "r"(a[2]), "r"(a[3]), "r"(b[0]), "r"(b[1]));
}
__device__ __forceinline__ float tf32_hi(float x) {
    uint32_t h;
    asm("cvt.rna.tf32.f32 %0, %1;" : "=r"(h) : "f"(x));
    return __uint_as_float(h);
}
__device__ __forceinline__ uint32_t tf32_bits(float x) {
    uint32_t h;
    asm("cvt.rna.tf32.f32 %0, %1;" : "=r"(h) : "f"(x));
    return h;
}
__device__ __forceinline__ void split1(float x, uint32_t& h, uint32_t& l) {
    float hf = tf32_hi(x);
    h = __float_as_uint(hf);
    l = __float_as_uint(x - hf);
}
__device__ __forceinline__ void cp16(uint32_t dst, const void* src) {
    asm volatile("cp.async.cg.shared.global [%0], [%1], 16;"
                 :: "r"(dst), "l"(src));
}
#define CP_COMMIT() asm volatile("cp.async.commit_group;" ::: "memory")
#define CP_WAIT1()  asm volatile("cp.async.wait_group 1;" ::: "memory")

__device__ __forceinline__ void stcs2(float* p, float a, float b) {
    asm volatile("st.global.cs.v2.f32 [%0], {%1, %2};" :: "l"(p), "f"(a), "f"(b)
                 : "memory");
}
__device__ __forceinline__ void stcs4(float* p, float4 v) {
    asm volatile("st.global.cs.v4.f32 [%0], {%1, %2, %3, %4};"
                 :: "l"(p), "f"(v.x), "f"(v.y), "f"(v.z), "f"(v.w) : "memory");
}

// ===========================================================================
// Projection GEMM (2xTF32): C[M,N] = A[M,K] @ W[K,N] + bias, N % 128 == 0
// PERM (Q-projection): output d -> 16*(d%4) + d/4 per 64-slice, tf32-ROUNDED.
// ===========================================================================
#define PJ_PA 20
#define PJ_PB 136
#define PJ_ASZ (128*PJ_PA)
#define PJ_BSZ (16*PJ_PB)

template<int PERM>
__global__ __launch_bounds__(256) void proj_mma(
    const float* __restrict__ A, const float* __restrict__ W,
    const float* __restrict__ bias, float* __restrict__ C,
    int M, int N, int K)
{
    __shared__ float As[2*PJ_ASZ];
    __shared__ float Bs[2*PJ_BSZ];
    const int tid = threadIdx.x;
    const int w = tid >> 5, t = tid & 31;
    const int m0 = blockIdx.y * 128, n0 = blockIdx.x * 128;
    const int wm = (w & 1) * 64, wn = (w >> 1) * 32;
    const int NC = K / 16;

    const float* Ab = A + (size_t)m0 * K;
    const float* Wb = W + n0;
    const uint32_t abase = (uint32_t)__cvta_generic_to_shared(As);
    const uint32_t bbase = (uint32_t)__cvta_generic_to_shared(Bs);

    auto issue = [&](int c, int buf) {
        #pragma unroll
        for (int i = 0; i < 2; i++) {
            int v = tid + i*256;
            int r = v >> 2, ca = (v & 3)*4;
            cp16(abase + (buf*PJ_ASZ + r*PJ_PA + ca)*4,
                 Ab + (size_t)r*K + c*16 + ca);
            int kr = v >> 5, cb = (v & 31)*4;
            cp16(bbase + (buf*PJ_BSZ + kr*PJ_PB + cb)*4,
                 Wb + (size_t)(c*16 + kr)*N + cb);
        }
    };

    float acc[4][4][4];
    #pragma unroll
    for (int i = 0; i < 4; i++)
        #pragma unroll
        for (int j = 0; j < 4; j++)
            #pragma unroll
            for (int r = 0; r < 4; r++) acc[i][j][r] = 0.f;

    issue(0, 0); CP_COMMIT();

    for (int c = 0; c < NC; c++) {
        int buf = c & 1;
        if (c + 1 < NC) issue(c + 1, buf ^ 1);
        CP_COMMIT();
        CP_WAIT1();
        __syncthreads();
        const float* Af = As + buf*PJ_ASZ;
        const float* Bf = Bs + buf*PJ_BSZ;
        #pragma unroll
        for (int ks = 0; ks < 2; ks++) {
            int kk = ks * 8;
            uint32_t afh[4][4], afl[4][4], bf[4][2];
            #pragma unroll
            for (int i = 0; i < 4; i++) {
                int o = (wm + i*16 + (t >> 2))*PJ_PA + kk + (t & 3);
                split1(Af[o],              afh[i][0], afl[i][0]);
                split1(Af[o + 8*PJ_PA],    afh[i][1], afl[i][1]);
                split1(Af[o + 4],          afh[i][2], afl[i][2]);
                split1(Af[o + 8*PJ_PA + 4],afh[i][3], afl[i][3]);
            }
            #pragma unroll
            for (int j = 0; j < 4; j++) {
                int o = (kk + (t & 3))*PJ_PB + wn + j*8 + (t >> 2);
                bf[j][0] = tf32_bits(Bf[o]);
                bf[j][1] = tf32_bits(Bf[o + 4*PJ_PB]);
            }
            #pragma unroll
            for (int i = 0; i < 4; i++)
                #pragma unroll
                for (int j = 0; j < 4; j++) {
                    mma_tf32(acc[i][j], afh[i], bf[j]);
                    mma_tf32(acc[i][j], afl[i], bf[j]);
                }
        }
        __syncthreads();
    }

    #pragma unroll
    for (int i = 0; i < 4; i++) {
        int r0 = m0 + wm + i*16 + (t >> 2);
        #pragma unroll
        for (int j = 0; j < 4; j++) {
            int col = n0 + wn + j*8 + (t & 3)*2;
            float2 bb = *(const float2*)&bias[col];
            float v00 = acc[i][j][0] + bb.x, v01 = acc[i][j][1] + bb.y;
            float v10 = acc[i][j][2] + bb.x, v11 = acc[i][j][3] + bb.y;
            if (PERM) {
                v00 = tf32_hi(v00); v01 = tf32_hi(v01);
                v10 = tf32_hi(v10); v11 = tf32_hi(v11);
                int d = col & 63, base = (col & ~63);
                int c0 = base + 16*(d & 3) + (d >> 2);
                C[(size_t)r0*N + c0]            = v00;
                C[(size_t)r0*N + c0 + 16]       = v01;
                C[(size_t)(r0 + 8)*N + c0]      = v10;
                C[(size_t)(r0 + 8)*N + c0 + 16] = v11;
            } else {
                *(float2*)&C[(size_t)r0*N + col]       = make_float2(v00, v01);
                *(float2*)&C[(size_t)(r0 + 8)*N + col] = make_float2(v10, v11);
            }
        }
    }
}

// ===========================================================================
// N=64 projection (2xTF32), tf32-ROUNDED outputs; PERM=1 applies in-row
// d-permutation 16*(d%4)+d/4 (K path); PERM=0 canonical (V path).
// ===========================================================================
#define P6_PA 20
#define P6_PB 72
#define P6_ASZ (64*P6_PA)
#define P6_BSZ (16*P6_PB)

template<int PERM>
__global__ __launch_bounds__(256) void projn64_mma(
    const float* __restrict__ A, const float* __restrict__ W,
    const float* __restrict__ bias, float* __restrict__ C,
    int M, int K)
{
    __shared__ float As[2*P6_ASZ];
    __shared__ float Bs[2*P6_BSZ];
    const int tid = threadIdx.x;
    const int w = tid >> 5, t = tid & 31;
    const int m0 = blockIdx.x * 64;
    const int wm = (w & 1) * 32, wn = (w >> 1) * 16;
    const int NC = K / 16;

    const float* Ab = A + (size_t)m0 * K;
    const uint32_t abase = (uint32_t)__cvta_generic_to_shared(As);
    const uint32_t bbase = (uint32_t)__cvta_generic_to_shared(Bs);

    auto issue = [&](int c, int buf) {
        int r = tid >> 2, ca = (tid & 3)*4;
        cp16(abase + (buf*P6_ASZ + r*P6_PA + ca)*4, Ab + (size_t)r*K + c*16 + ca);
        int kr = tid >> 4, cb = (tid & 15)*4;
        cp16(bbase + (buf*P6_BSZ + kr*P6_PB + cb)*4,
             W + (size_t)(c*16 + kr)*64 + cb);
    };

    float acc[2][2][4];
    #pragma unroll
    for (int i = 0; i < 2; i++)
        #pragma unroll
        for (int j = 0; j < 2; j++)
            #pragma unroll
            for (int r = 0; r < 4; r++) acc[i][j][r] = 0.f;

    issue(0, 0); CP_COMMIT();

    for (int c = 0; c < NC; c++) {
        int buf = c & 1;
        if (c + 1 < NC) issue(c + 1, buf ^ 1);
        CP_COMMIT();
        CP_WAIT1();
        __syncthreads();
        const float* Af = As + buf*P6_ASZ;
        const float* Bf = Bs + buf*P6_BSZ;
        #pragma unroll
        for (int ks = 0; ks < 2; ks++) {
            int kk = ks * 8;
            uint32_t afh[2][4], afl[2][4], bf[2][2];
            #pragma unroll
            for (int i = 0; i < 2; i++) {
                int o = (wm + i*16 + (t >> 2))*P6_PA + kk + (t & 3);
                split1(Af[o],              afh[i][0], afl[i][0]);
                split1(Af[o + 8*P6_PA],    afh[i][1], afl[i][1]);
                split1(Af[o + 4],          afh[i][2], afl[i][2]);
                split1(Af[o + 8*P6_PA + 4],afh[i][3], afl[i][3]);
            }
            #pragma unroll
            for (int j = 0; j < 2; j++) {
                int o = (kk + (t & 3))*P6_PB + wn + j*8 + (t >> 2);
                bf[j][0] = tf32_bits(Bf[o]);
                bf[j][1] = tf32_bits(Bf[o + 4*P6_PB]);
            }
            #pragma unroll
            for (int i = 0; i < 2; i++)
                #pragma unroll
                for (int j = 0; j < 2; j++) {
                    mma_tf32(acc[i][j], afh[i], bf[j]);
                    mma_tf32(acc[i][j], afl[i], bf[j]);
                }
        }
        __syncthreads();
    }

    #pragma unroll
    for (int i = 0; i < 2; i++) {
        int r0 = m0 + wm + i*16 + (t >> 2);
        #pragma unroll
        for (int j = 0; j < 2; j++) {
            int col = wn + j*8 + (t & 3)*2;
            float2 bb = *(const float2*)&bias[col];
            float v00 = tf32_hi(acc[i][j][0] + bb.x);
            float v01 = tf32_hi(acc[i][j][1] + bb.y);
            float v10 = tf32_hi(acc[i][j][2] + bb.x);
            float v11 = tf32_hi(acc[i][j][3] + bb.y);
            if (PERM) {
                int c0 = 16*(col & 3) + (col >> 2);
                C[(size_t)r0*64 + c0]            = v00;
                C[(size_t)r0*64 + c0 + 16]       = v01;
                C[(size_t)(r0 + 8)*64 + c0]      = v10;
                C[(size_t)(r0 + 8)*64 + c0 + 16] = v11;
            } else {
                *(float2*)&C[(size_t)r0*64 + col]       = make_float2(v00, v01);
                *(float2*)&C[(size_t)(r0 + 8)*64 + col] = make_float2(v10, v11);
            }
        }
    }
}

// ===========================================================================
// Pass A (1 MMA): u = tf32(exp((Q~ @ K~^T)*scale)) -> p_attn; row sums -> g_L.
// 64-ROW q tiles: smem 57KB -> 3 CTAs/SM. Warps: 2q x 4n, warp tile 32x16.
// Q~/K~ pre-rounded tf32, d-permuted; all fragment loads LDS.128.
// ===========================================================================
#define SC_QP 76
#define SC_QSZ (64*SC_QP)
#define SC_KSZ (64*SC_QP)
#define SC_SMEM ((SC_QSZ + 2*SC_KSZ) * 4)

__global__ __launch_bounds__(256, 3) void attn_scores_mma(float* __restrict__ P)
{
    extern __shared__ float sd[];
    float* Qs = sd;                  // 64 x pitch76 (tf32, permuted)
    float* Ks = sd + SC_QSZ;         // 2 x 64 x pitch76 (tf32, permuted)

    const int tid = threadIdx.x;
    const int w = tid >> 5, t = tid & 31;
    const int tq = t & 3, tr = t >> 2;
    const int qt = blockIdx.x, head = blockIdx.y, b = blockIdx.z;
    const int wq = (w & 1) * 32, wn = (w >> 1) * 16;

    const uint32_t qbase = (uint32_t)__cvta_generic_to_shared(Qs);
    const uint32_t kbase = (uint32_t)__cvta_generic_to_shared(Ks);

    {
        const float* Qg = g_Q + (size_t)(b*NS + qt*64) * NDM + head*NDK;
        #pragma unroll
        for (int i = 0; i < 4; i++) {
            int v = tid + i*256;
            int r = v >> 4, m = v & 15;
            cp16(qbase + (r*SC_QP + 20*(m >> 2) + 4*(m & 3))*4,
                 Qg + (size_t)r*NDM + m*4);
        }
    }
    CP_COMMIT();
    auto issueK = [&](int kt, int buf) {
        const float* Kg = g_K + (size_t)(b*NS + kt*64) * NDK;
        #pragma unroll
        for (int i = 0; i < 4; i++) {
            int v = tid + i*256;
            int r = v >> 4, m = v & 15;
            cp16(kbase + (buf*SC_KSZ + r*SC_QP + 20*(m >> 2) + 4*(m & 3))*4,
                 Kg + (size_t)r*NDK + m*4);
        }
    };
    issueK(0, 0); CP_COMMIT();

    float lsum[2][2];
    #pragma unroll
    for (int i = 0; i < 2; i++)
        #pragma unroll
        for (int hf = 0; hf < 2; hf++) lsum[i][hf] = 0.f;

    float* pb = P + ((size_t)(b*NH + head)*NS + (size_t)qt*64) * NS;

    for (int kt = 0; kt < 32; kt++) {
        int buf = kt & 1;
        if (kt + 1 < 32) issueK(kt + 1, buf ^ 1);
        CP_COMMIT();
        CP_WAIT1();
        __syncthreads();
        const float* Kf = Ks + buf*SC_KSZ;

        float acc[2][2][4];
        #pragma unroll
        for (int i = 0; i < 2; i++)
            #pragma unroll
            for (int j = 0; j < 2; j++)
                #pragma unroll
                for (int r = 0; r < 4; r++) acc[i][j][r] = 0.f;

        #pragma unroll
        for (int ksb = 0; ksb < 4; ksb++) {
            float4 qr0[2], qr1[2], kb[2];
            #pragma unroll
            for (int i = 0; i < 2; i++) {
                int r = wq + i*16 + tr;
                qr0[i] = *(const float4*)&Qs[r*SC_QP + 20*tq + 4*ksb];
                qr1[i] = *(const float4*)&Qs[(r + 8)*SC_QP + 20*tq + 4*ksb];
            }
            #pragma unroll
            for (int j = 0; j < 2; j++) {
                int n = wn + j*8 + tr;
                kb[j] = *(const float4*)&Kf[n*SC_QP + 20*tq + 4*ksb];
            }
            #pragma unroll
            for (int kss = 0; kss < 2; kss++) {
                uint32_t bf[2][2];
                #pragma unroll
                for (int j = 0; j < 2; j++) {
                    bf[j][0] = __float_as_uint(kss ? kb[j].z : kb[j].x);
                    bf[j][1] = __float_as_uint(kss ? kb[j].w : kb[j].y);
                }
                #pragma unroll
                for (int i = 0; i < 2; i++) {
                    uint32_t af[4];
                    af[0] = __float_as_uint(kss ? qr0[i].z : qr0[i].x);
                    af[2] = __float_as_uint(kss ? qr0[i].w : qr0[i].y);
                    af[1] = __float_as_uint(kss ? qr1[i].z : qr1[i].x);
                    af[3] = __float_as_uint(kss ? qr1[i].w : qr1[i].y);
                    #pragma unroll
                    for (int j = 0; j < 2; j++)
                        mma_tf32(acc[i][j], af, bf[j]);
                }
            }
        }

        // epilogue: u = tf32(exp(s*scale)); streaming store; row sums of u
        #pragma unroll
        for (int i = 0; i < 2; i++) {
            #pragma unroll
            for (int hf = 0; hf < 2; hf++) {
                float vals[4];
                #pragma unroll
                for (int j = 0; j < 2; j++) {
                    vals[j*2+0] = tf32_hi(__expf(acc[i][j][hf*2+0] * 0.125f));
                    vals[j*2+1] = tf32_hi(__expf(acc[i][j][hf*2+1] * 0.125f));
                }
                lsum[i][hf] += vals[0] + vals[1] + vals[2] + vals[3];

                int row = wq + i*16 + hf*8 + tr;
                float* rp = pb + (size_t)row*NS + kt*64 + wn + tq*2;
                stcs2(rp,     vals[0], vals[1]);
                stcs2(rp + 8, vals[2], vals[3]);
            }
        }
        __syncthreads();
    }

    // reduce sums: quad lanes, then 4 n-warp-groups (red aliases Ks)
    float* red = Ks;
    #pragma unroll
    for (int i = 0; i < 2; i++)
        #pragma unroll
        for (int hf = 0; hf < 2; hf++) {
            float l = lsum[i][hf];
            l += __shfl_xor_sync(0xffffffffu, l, 1);
            l += __shfl_xor_sync(0xffffffffu, l, 2);
            if (tq == 0) {
                int row = wq + i*16 + hf*8 + tr;
                red[row*4 + (w >> 1)] = l;
            }
        }
    __syncthreads();
    if (tid < 64) {
        int gq = (b*NH + head)*NS + qt*64 + tid;
        g_L[gq] = (red[tid*4] + red[tid*4+1]) + (red[tid*4+2] + red[tid*4+3]);
    }
}

// ===========================================================================
// Pass B (1 MMA, R11 version): X = (U~ @ V~) / L; p = u/L streamed out.
// U~ and V~ both pre-rounded tf32 -> zero cvt/split in mainloop.
// ===========================================================================
#define PV_PP 68
#define PV_VP 72
#define PV_PSZ (128*PV_PP)
#define PV_VSZ (64*PV_VP)
#define PV_SMEM ((2*PV_PSZ + 2*PV_VSZ + 256) * 4)

__global__ __launch_bounds__(256) void attn_pv_mma(float* __restrict__ P)
{
    extern __shared__ float sd[];
    float* Ps = sd;                       // 2 x 128*68
    float* Vs = sd + 2*PV_PSZ;            // 2 x 64*72
    float* sl = sd + 2*PV_PSZ + 2*PV_VSZ; // 128

    const int tid = threadIdx.x;
    const int w = tid >> 5, t = tid & 31;
    const int qt = blockIdx.x, head = blockIdx.y, b = blockIdx.z;
    const int wq = (w & 3) * 32, wd = (w >> 2) * 32;

    const uint32_t pbase = (uint32_t)__cvta_generic_to_shared(Ps);
    const uint32_t vbase = (uint32_t)__cvta_generic_to_shared(Vs);

    float* pb = P + ((size_t)(b*NH + head)*NS + (size_t)qt*128) * NS;

    auto issue = [&](int kt, int buf) {
        #pragma unroll
        for (int i = 0; i < 8; i++) {
            int v = tid + i*256;
            int r = v >> 4, c = (v & 15)*4;
            cp16(pbase + (buf*PV_PSZ + r*PV_PP + c)*4,
                 pb + (size_t)r*NS + kt*64 + c);
        }
        const float* Vg = g_V + (size_t)(b*NS + kt*64) * NDK;
        #pragma unroll
        for (int i = 0; i < 4; i++) {
            int v = tid + i*256;
            int r = v >> 4, c = (v & 15)*4;
            cp16(vbase + (buf*PV_VSZ + r*PV_VP + c)*4, Vg + (size_t)r*NDK + c);
        }
    };

    issue(0, 0); CP_COMMIT();
    if (tid < 128) {
        int gq = (b*NH + head)*NS + qt*128 + tid;
        sl[tid] = 1.0f / g_L[gq];
    }

    float acc[2][4][4];
    #pragma unroll
    for (int i = 0; i < 2; i++)
        #pragma unroll
        for (int j = 0; j < 4; j++)
            #pragma unroll
            for (int r = 0; r < 4; r++) acc[i][j][r] = 0.f;

    for (int kt = 0; kt < 32; kt++) {
        int buf = kt & 1;
        if (kt + 1 < 32) issue(kt + 1, buf ^ 1);
        CP_COMMIT();
        CP_WAIT1();
        __syncthreads();
        const float* Pf = Ps + buf*PV_PSZ;
        const float* Vf = Vs + buf*PV_VSZ;

        // side-channel: p = u * (1/L), streaming store only
        #pragma unroll
        for (int i = 0; i < 8; i++) {
            int v = tid + i*256;
            int r = v >> 4, c = (v & 15)*4;
            float4 s = *(const float4*)&Pf[r*PV_PP + c];
            float il = sl[r];
            stcs4(pb + (size_t)r*NS + kt*64 + c,
                  make_float4(s.x*il, s.y*il, s.z*il, s.w*il));
        }

        // single MMA: U~ x V~ (both already tf32 bit patterns)
        #pragma unroll
        for (int ks = 0; ks < 8; ks++) {
            int kk = ks * 8;
            uint32_t af[2][4], bf[4][2];
            #pragma unroll
            for (int i = 0; i < 2; i++) {
                int o = (wq + i*16 + (t >> 2))*PV_PP + kk + (t & 3);
                af[i][0] = __float_as_uint(Pf[o]);
                af[i][1] = __float_as_uint(Pf[o + 8*PV_PP]);
                af[i][2] = __float_as_uint(Pf[o + 4]);
                af[i][3] = __float_as_uint(Pf[o + 8*PV_PP + 4]);
            }
            #pragma unroll
            for (int j = 0; j < 4; j++) {
                int o = (kk + (t & 3))*PV_VP + wd + j*8 + (t >> 2);
                bf[j][0] = __float_as_uint(Vf[o]);
                bf[j][1] = __float_as_uint(Vf[o + 4*PV_VP]);
            }
            #pragma unroll
            for (int i = 0; i < 2; i++)
                #pragma unroll
                for (int j = 0; j < 4; j++)
                    mma_tf32(acc[i][j], af[i], bf[j]);
        }
        __syncthreads();
    }

    // epilogue: X = acc / L
    #pragma unroll
    for (int i = 0; i < 2; i++) {
        int lr = wq + i*16 + (t >> 2);
        float il0 = sl[lr], il1 = sl[lr + 8];
        int row = qt*128 + lr;
        #pragma unroll
        for (int j = 0; j < 4; j++) {
            int col = head*NDK + wd + j*8 + (t & 3)*2;
            *(float2*)&g_X[(size_t)(b*NS + row)*NDM + col] =
                make_float2(acc[i][j][0]*il0, acc[i][j][1]*il0);
            *(float2*)&g_X[(size_t)(b*NS + row + 8)*NDM + col] =
                make_float2(acc[i][j][2]*il1, acc[i][j][3]*il1);
        }
    }
}

// ---------------------------------------------------------------------------
extern "C" void kernel_launch(void* const* d_in, const int* in_sizes, int n_in,
                              void* d_out, int out_size)
{
    const float* query = (const float*)d_in[0];
    const float* key_i = (const float*)d_in[1];
    const float* value = (const float*)d_in[2];
    const float* qW = (const float*)d_in[3];
    const float* qb = (const float*)d_in[4];
    const float* kW = (const float*)d_in[5];
    const float* kb = (const float*)d_in[6];
    const float* vW = (const float*)d_in[7];
    const float* vb = (const float*)d_in[8];
    const float* oW = (const float*)d_in[9];
    const float* ob = (const float*)d_in[10];

    float* out   = (float*)d_out;                    // [B,S,D_MODEL]
    float* pattn = out + (size_t)NB * NS * NDM;      // [B,H,S,S]

    float *pQ, *pK, *pV, *pX;
    cudaGetSymbolAddress((void**)&pQ, g_Q);
    cudaGetSymbolAddress((void**)&pK, g_K);
    cudaGetSymbolAddress((void**)&pV, g_V);
    cudaGetSymbolAddress((void**)&pX, g_X);

    cudaFuncSetAttribute(attn_scores_mma,
                         cudaFuncAttributeMaxDynamicSharedMemorySize, SC_SMEM);
    cudaFuncSetAttribute(attn_pv_mma,
                         cudaFuncAttributeMaxDynamicSharedMemorySize, PV_SMEM);

    dim3 gG(NDM/128, NROWS/128);     // (8, 32)
    dim3 gS(NS/64, NH, NB);          // (32, 16, 2)
    dim3 gA(NS/128, NH, NB);         // (16, 16, 2)

    // 1) Q projection (2xTF32), d-permuted + tf32-rounded output
    proj_mma<1><<<gG, 256>>>(query, qW, qb, pQ, NROWS, NDM, NDM);
    // 2) K projection (2xTF32), d-permuted + tf32-rounded output
    projn64_mma<1><<<NROWS/64, 256>>>(key_i, kW, kb, pK, NROWS, NDM);
    // 3) V projection (2xTF32), tf32-rounded output (canonical)
    projn64_mma<0><<<NROWS/64, 256>>>(value, vW, vb, pV, NROWS, NDM);
    // 4) u = tf32(exp(scores)) + row sums (64-row tiles, 3 CTAs/SM)
    attn_scores_mma<<<gS, 256, SC_SMEM>>>(pattn);
    // 5) X = (U @ V)/L (single MMA), p = u/L streamed out
    attn_pv_mma<<<gA, 256, PV_SMEM>>>(pattn);
    // 6) output projection (2xTF32)
    proj_mma<0><<<gG, 256>>>(pX, oW, ob, out, NROWS, NDM, NDM);
}

// round 15
// speedup vs baseline: 1.0639x; 1.0639x over previous
#include <cuda_runtime.h>
#include <math.h>
#include <stdint.h>

#define NB 2
#define NS 2048
#define NH 16
#define NDK 64
#define NDM 1024
#define NROWS (NB*NS)   // 4096

// Scratch (no allocs allowed)
__device__ float g_Q[(size_t)NROWS*NDM];   // d-permuted per head slice, tf32-rounded
__device__ float g_K[(size_t)NROWS*NDK];   // d-permuted, tf32-rounded
__device__ float g_V[(size_t)NROWS*NDK];   // canonical, tf32-rounded
__device__ float g_X[(size_t)NROWS*NDM];   // canonical
__device__ float g_L[NB*NH*NS];

// ===========================================================================
// helpers
// ===========================================================================
__device__ __forceinline__ void mma_tf32(float (&d)[4], const uint32_t (&a)[4],
                                         const uint32_t (&b)[2]) {
    asm volatile("mma.sync.aligned.m16n8k8.row.col.f32.tf32.tf32.f32 "
        "{%0,%1,%2,%3}, {%4,%5,%6,%7}, {%8,%9}, {%0,%1,%2,%3};"
        : "+f"(d[0]), "+f"(d[1]), "+f"(d[2]), "+f"(d[3])
        : "r"(a[0]), "r"(a[1]), "r"(a[2]), "r"(a[3]), "r"(b[0]), "r"(b[1]));
}
__device__ __forceinline__ float tf32_hi(float x) {
    uint32_t h;
    asm("cvt.rna.tf32.f32 %0, %1;" : "=r"(h) : "f"(x));
    return __uint_as_float(h);
}
__device__ __forceinline__ uint32_t tf32_bits(float x) {
    uint32_t h;
    asm("cvt.rna.tf32.f32 %0, %1;" : "=r"(h) : "f"(x));
    return h;
}
__device__ __forceinline__ void split1(float x, uint32_t& h, uint32_t& l) {
    float hf = tf32_hi(x);
    h = __float_as_uint(hf);
    l = __float_as_uint(x - hf);
}
__device__ __forceinline__ void cp16(uint32_t dst, const void* src) {
    asm volatile("cp.async.cg.shared.global [%0], [%1], 16;"
                 :: "r"(dst), "l"(src));
}
#define CP_COMMIT() asm volatile("cp.async.commit_group;" ::: "memory")
#define CP_WAIT1()  asm volatile("cp.async.wait_group 1;" ::: "memory")

// u store: .cg (keep in L2 for pass B's re-read)
__device__ __forceinline__ void stcg2(float* p, float a, float b) {
    asm volatile("st.global.cg.v2.f32 [%0], {%1, %2};" :: "l"(p), "f"(a), "f"(b)
                 : "memory");
}
// p store: .cs (write-once stream, never re-read)
__device__ __forceinline__ void stcs4(float* p, float4 v) {
    asm volatile("st.global.cs.v4.f32 [%0], {%1, %2, %3, %4};"
                 :: "l"(p), "f"(v.x), "f"(v.y), "f"(v.z), "f"(v.w) : "memory");
}

// ===========================================================================
// Projection GEMM (2xTF32): C[M,N] = A[M,K] @ W[K,N] + bias, N % 128 == 0
// PERM (Q-projection): output d -> 16*(d%4) + d/4 per 64-slice, tf32-ROUNDED.
// ===========================================================================
#define PJ_PA 20
#define PJ_PB 136
#define PJ_ASZ (128*PJ_PA)
#define PJ_BSZ (16*PJ_PB)

template<int PERM>
__global__ __launch_bounds__(256) void proj_mma(
    const float* __restrict__ A, const float* __restrict__ W,
    const float* __restrict__ bias, float* __restrict__ C,
    int M, int N, int K)
{
    __shared__ float As[2*PJ_ASZ];
    __shared__ float Bs[2*PJ_BSZ];
    const int tid = threadIdx.x;
    const int w = tid >> 5, t = tid & 31;
    const int m0 = blockIdx.y * 128, n0 = blockIdx.x * 128;
    const int wm = (w & 1) * 64, wn = (w >> 1) * 32;
    const int NC = K / 16;

    const float* Ab = A + (size_t)m0 * K;
    const float* Wb = W + n0;
    const uint32_t abase = (uint32_t)__cvta_generic_to_shared(As);
    const uint32_t bbase = (uint32_t)__cvta_generic_to_shared(Bs);

    auto issue = [&](int c, int buf) {
        #pragma unroll
        for (int i = 0; i < 2; i++) {
            int v = tid + i*256;
            int r = v >> 2, ca = (v & 3)*4;
            cp16(abase + (buf*PJ_ASZ + r*PJ_PA + ca)*4,
                 Ab + (size_t)r*K + c*16 + ca);
            int kr = v >> 5, cb = (v & 31)*4;
            cp16(bbase + (buf*PJ_BSZ + kr*PJ_PB + cb)*4,
                 Wb + (size_t)(c*16 + kr)*N + cb);
        }
    };

    float acc[4][4][4];
    #pragma unroll
    for (int i = 0; i < 4; i++)
        #pragma unroll
        for (int j = 0; j < 4; j++)
            #pragma unroll
            for (int r = 0; r < 4; r++) acc[i][j][r] = 0.f;

    issue(0, 0); CP_COMMIT();

    for (int c = 0; c < NC; c++) {
        int buf = c & 1;
        if (c + 1 < NC) issue(c + 1, buf ^ 1);
        CP_COMMIT();
        CP_WAIT1();
        __syncthreads();
        const float* Af = As + buf*PJ_ASZ;
        const float* Bf = Bs + buf*PJ_BSZ;
        #pragma unroll
        for (int ks = 0; ks < 2; ks++) {
            int kk = ks * 8;
            uint32_t afh[4][4], afl[4][4], bf[4][2];
            #pragma unroll
            for (int i = 0; i < 4; i++) {
                int o = (wm + i*16 + (t >> 2))*PJ_PA + kk + (t & 3);
                split1(Af[o],              afh[i][0], afl[i][0]);
                split1(Af[o + 8*PJ_PA],    afh[i][1], afl[i][1]);
                split1(Af[o + 4],          afh[i][2], afl[i][2]);
                split1(Af[o + 8*PJ_PA + 4],afh[i][3], afl[i][3]);
            }
            #pragma unroll
            for (int j = 0; j < 4; j++) {
                int o = (kk + (t & 3))*PJ_PB + wn + j*8 + (t >> 2);
                bf[j][0] = tf32_bits(Bf[o]);
                bf[j][1] = tf32_bits(Bf[o + 4*PJ_PB]);
            }
            #pragma unroll
            for (int i = 0; i < 4; i++)
                #pragma unroll
                for (int j = 0; j < 4; j++) {
                    mma_tf32(acc[i][j], afh[i], bf[j]);
                    mma_tf32(acc[i][j], afl[i], bf[j]);
                }
        }
        __syncthreads();
    }

    #pragma unroll
    for (int i = 0; i < 4; i++) {
        int r0 = m0 + wm + i*16 + (t >> 2);
        #pragma unroll
        for (int j = 0; j < 4; j++) {
            int col = n0 + wn + j*8 + (t & 3)*2;
            float2 bb = *(const float2*)&bias[col];
            float v00 = acc[i][j][0] + bb.x, v01 = acc[i][j][1] + bb.y;
            float v10 = acc[i][j][2] + bb.x, v11 = acc[i][j][3] + bb.y;
            if (PERM) {
                v00 = tf32_hi(v00); v01 = tf32_hi(v01);
                v10 = tf32_hi(v10); v11 = tf32_hi(v11);
                int d = col & 63, base = (col & ~63);
                int c0 = base + 16*(d & 3) + (d >> 2);
                C[(size_t)r0*N + c0]            = v00;
                C[(size_t)r0*N + c0 + 16]       = v01;
                C[(size_t)(r0 + 8)*N + c0]      = v10;
                C[(size_t)(r0 + 8)*N + c0 + 16] = v11;
            } else {
                *(float2*)&C[(size_t)r0*N + col]       = make_float2(v00, v01);
                *(float2*)&C[(size_t)(r0 + 8)*N + col] = make_float2(v10, v11);
            }
        }
    }
}

// ===========================================================================
// N=64 projection (2xTF32), tf32-ROUNDED outputs; PERM=1 applies in-row
// d-permutation 16*(d%4)+d/4 (K path); PERM=0 canonical (V path).
// ===========================================================================
#define P6_PA 20
#define P6_PB 72
#define P6_ASZ (64*P6_PA)
#define P6_BSZ (16*P6_PB)

template<int PERM>
__global__ __launch_bounds__(256) void projn64_mma(
    const float* __restrict__ A, const float* __restrict__ W,
    const float* __restrict__ bias, float* __restrict__ C,
    int M, int K)
{
    __shared__ float As[2*P6_ASZ];
    __shared__ float Bs[2*P6_BSZ];
    const int tid = threadIdx.x;
    const int w = tid >> 5, t = tid & 31;
    const int m0 = blockIdx.x * 64;
    const int wm = (w & 1) * 32, wn = (w >> 1) * 16;
    const int NC = K / 16;

    const float* Ab = A + (size_t)m0 * K;
    const uint32_t abase = (uint32_t)__cvta_generic_to_shared(As);
    const uint32_t bbase = (uint32_t)__cvta_generic_to_shared(Bs);

    auto issue = [&](int c, int buf) {
        int r = tid >> 2, ca = (tid & 3)*4;
        cp16(abase + (buf*P6_ASZ + r*P6_PA + ca)*4, Ab + (size_t)r*K + c*16 + ca);
        int kr = tid >> 4, cb = (tid & 15)*4;
        cp16(bbase + (buf*P6_BSZ + kr*P6_PB + cb)*4,
             W + (size_t)(c*16 + kr)*64 + cb);
    };

    float acc[2][2][4];
    #pragma unroll
    for (int i = 0; i < 2; i++)
        #pragma unroll
        for (int j = 0; j < 2; j++)
            #pragma unroll
            for (int r = 0; r < 4; r++) acc[i][j][r] = 0.f;

    issue(0, 0); CP_COMMIT();

    for (int c = 0; c < NC; c++) {
        int buf = c & 1;
        if (c + 1 < NC) issue(c + 1, buf ^ 1);
        CP_COMMIT();
        CP_WAIT1();
        __syncthreads();
        const float* Af = As + buf*P6_ASZ;
        const float* Bf = Bs + buf*P6_BSZ;
        #pragma unroll
        for (int ks = 0; ks < 2; ks++) {
            int kk = ks * 8;
            uint32_t afh[2][4], afl[2][4], bf[2][2];
            #pragma unroll
            for (int i = 0; i < 2; i++) {
                int o = (wm + i*16 + (t >> 2))*P6_PA + kk + (t & 3);
                split1(Af[o],              afh[i][0], afl[i][0]);
                split1(Af[o + 8*P6_PA],    afh[i][1], afl[i][1]);
                split1(Af[o + 4],          afh[i][2], afl[i][2]);
                split1(Af[o + 8*P6_PA + 4],afh[i][3], afl[i][3]);
            }
            #pragma unroll
            for (int j = 0; j < 2; j++) {
                int o = (kk + (t & 3))*P6_PB + wn + j*8 + (t >> 2);
                bf[j][0] = tf32_bits(Bf[o]);
                bf[j][1] = tf32_bits(Bf[o + 4*P6_PB]);
            }
            #pragma unroll
            for (int i = 0; i < 2; i++)
                #pragma unroll
                for (int j = 0; j < 2; j++) {
                    mma_tf32(acc[i][j], afh[i], bf[j]);
                    mma_tf32(acc[i][j], afl[i], bf[j]);
                }
        }
        __syncthreads();
    }

    #pragma unroll
    for (int i = 0; i < 2; i++) {
        int r0 = m0 + wm + i*16 + (t >> 2);
        #pragma unroll
        for (int j = 0; j < 2; j++) {
            int col = wn + j*8 + (t & 3)*2;
            float2 bb = *(const float2*)&bias[col];
            float v00 = tf32_hi(acc[i][j][0] + bb.x);
            float v01 = tf32_hi(acc[i][j][1] + bb.y);
            float v10 = tf32_hi(acc[i][j][2] + bb.x);
            float v11 = tf32_hi(acc[i][j][3] + bb.y);
            if (PERM) {
                int c0 = 16*(col & 3) + (col >> 2);
                C[(size_t)r0*64 + c0]            = v00;
                C[(size_t)r0*64 + c0 + 16]       = v01;
                C[(size_t)(r0 + 8)*64 + c0]      = v10;
                C[(size_t)(r0 + 8)*64 + c0 + 16] = v11;
            } else {
                *(float2*)&C[(size_t)r0*64 + col]       = make_float2(v00, v01);
                *(float2*)&C[(size_t)(r0 + 8)*64 + col] = make_float2(v10, v11);
            }
        }
    }
}

// ===========================================================================
// Pass A (1 MMA): u = tf32(exp((Q~ @ K~^T)*scale)) -> p_attn (.cg store);
// row sums -> g_L. 128-row q tiles, 2 CTAs/SM (R11 config).
// ===========================================================================
#define SC_QP 76
#define SC_QSZ (128*SC_QP)
#define SC_KSZ (64*SC_QP)
#define SC_SMEM ((SC_QSZ + 2*SC_KSZ) * 4)

__global__ __launch_bounds__(256, 2) void attn_scores_mma(float* __restrict__ P)
{
    extern __shared__ float sd[];
    float* Qs = sd;                  // 128 x pitch76 (tf32, permuted)
    float* Ks = sd + SC_QSZ;         // 2 x 64 x pitch76 (tf32, permuted)

    const int tid = threadIdx.x;
    const int w = tid >> 5, t = tid & 31;
    const int tq = t & 3, tr = t >> 2;
    const int qt = blockIdx.x, head = blockIdx.y, b = blockIdx.z;
    const int wq = (w & 3) * 32, wn = (w >> 2) * 32;

    const uint32_t qbase = (uint32_t)__cvta_generic_to_shared(Qs);
    const uint32_t kbase = (uint32_t)__cvta_generic_to_shared(Ks);

    {
        const float* Qg = g_Q + (size_t)(b*NS + qt*128) * NDM + head*NDK;
        #pragma unroll
        for (int i = 0; i < 8; i++) {
            int v = tid + i*256;
            int r = v >> 4, m = v & 15;
            cp16(qbase + (r*SC_QP + 20*(m >> 2) + 4*(m & 3))*4,
                 Qg + (size_t)r*NDM + m*4);
        }
    }
    CP_COMMIT();
    auto issueK = [&](int kt, int buf) {
        const float* Kg = g_K + (size_t)(b*NS + kt*64) * NDK;
        #pragma unroll
        for (int i = 0; i < 4; i++) {
            int v = tid + i*256;
            int r = v >> 4, m = v & 15;
            cp16(kbase + (buf*SC_KSZ + r*SC_QP + 20*(m >> 2) + 4*(m & 3))*4,
                 Kg + (size_t)r*NDK + m*4);
        }
    };
    issueK(0, 0); CP_COMMIT();

    float lsum[2][2];
    #pragma unroll
    for (int i = 0; i < 2; i++)
        #pragma unroll
        for (int hf = 0; hf < 2; hf++) lsum[i][hf] = 0.f;

    float* pb = P + ((size_t)(b*NH + head)*NS + (size_t)qt*128) * NS;

    for (int kt = 0; kt < 32; kt++) {
        int buf = kt & 1;
        if (kt + 1 < 32) issueK(kt + 1, buf ^ 1);
        CP_COMMIT();
        CP_WAIT1();
        __syncthreads();
        const float* Kf = Ks + buf*SC_KSZ;

        float acc[2][4][4];
        #pragma unroll
        for (int i = 0; i < 2; i++)
            #pragma unroll
            for (int j = 0; j < 4; j++)
                #pragma unroll
                for (int r = 0; r < 4; r++) acc[i][j][r] = 0.f;

        #pragma unroll
        for (int ksb = 0; ksb < 4; ksb++) {
            float4 qr0[2], qr1[2], kb[4];
            #pragma unroll
            for (int i = 0; i < 2; i++) {
                int r = wq + i*16 + tr;
                qr0[i] = *(const float4*)&Qs[r*SC_QP + 20*tq + 4*ksb];
                qr1[i] = *(const float4*)&Qs[(r + 8)*SC_QP + 20*tq + 4*ksb];
            }
            #pragma unroll
            for (int j = 0; j < 4; j++) {
                int n = wn + j*8 + tr;
                kb[j] = *(const float4*)&Kf[n*SC_QP + 20*tq + 4*ksb];
            }
            #pragma unroll
            for (int kss = 0; kss < 2; kss++) {
                uint32_t bf[4][2];
                #pragma unroll
                for (int j = 0; j < 4; j++) {
                    bf[j][0] = __float_as_uint(kss ? kb[j].z : kb[j].x);
                    bf[j][1] = __float_as_uint(kss ? kb[j].w : kb[j].y);
                }
                #pragma unroll
                for (int i = 0; i < 2; i++) {
                    uint32_t af[4];
                    af[0] = __float_as_uint(kss ? qr0[i].z : qr0[i].x);
                    af[2] = __float_as_uint(kss ? qr0[i].w : qr0[i].y);
                    af[1] = __float_as_uint(kss ? qr1[i].z : qr1[i].x);
                    af[3] = __float_as_uint(kss ? qr1[i].w : qr1[i].y);
                    #pragma unroll
                    for (int j = 0; j < 4; j++)
                        mma_tf32(acc[i][j], af, bf[j]);
                }
            }
        }

        // epilogue: u = tf32(exp(s*scale)); .cg store (pv re-reads); row sums
        #pragma unroll
        for (int i = 0; i < 2; i++) {
            #pragma unroll
            for (int hf = 0; hf < 2; hf++) {
                float vals[8];
                #pragma unroll
                for (int j = 0; j < 4; j++) {
                    vals[j*2+0] = tf32_hi(__expf(acc[i][j][hf*2+0] * 0.125f));
                    vals[j*2+1] = tf32_hi(__expf(acc[i][j][hf*2+1] * 0.125f));
                }
                float s = 0.f;
                #pragma unroll
                for (int e = 0; e < 8; e++) s += vals[e];
                lsum[i][hf] += s;

                int row = wq + i*16 + hf*8 + tr;
                float* rp = pb + (size_t)row*NS + kt*64 + wn + tq*2;
                #pragma unroll
                for (int j = 0; j < 4; j++)
                    stcg2(rp + j*8, vals[j*2], vals[j*2+1]);
            }
        }
        __syncthreads();
    }

    // reduce sums: quad lanes, then 2 n-warps (red aliases Ks, K dead now)
    float* red = Ks;
    #pragma unroll
    for (int i = 0; i < 2; i++)
        #pragma unroll
        for (int hf = 0; hf < 2; hf++) {
            float l = lsum[i][hf];
            l += __shfl_xor_sync(0xffffffffu, l, 1);
            l += __shfl_xor_sync(0xffffffffu, l, 2);
            if (tq == 0) {
                int row = wq + i*16 + hf*8 + tr;
                red[row*2 + (w >> 2)] = l;
            }
        }
    __syncthreads();
    if (tid < 128) {
        int gq = (b*NH + head)*NS + qt*128 + tid;
        g_L[gq] = red[tid*2] + red[tid*2+1];
    }
}

// ===========================================================================
// Pass B (1 MMA, R11 version): X = (U~ @ V~) / L; p = u/L streamed out.
// ===========================================================================
#define PV_PP 68
#define PV_VP 72
#define PV_PSZ (128*PV_PP)
#define PV_VSZ (64*PV_VP)
#define PV_SMEM ((2*PV_PSZ + 2*PV_VSZ + 256) * 4)

__global__ __launch_bounds__(256) void attn_pv_mma(float* __restrict__ P)
{
    extern __shared__ float sd[];
    float* Ps = sd;                       // 2 x 128*68
    float* Vs = sd + 2*PV_PSZ;            // 2 x 64*72
    float* sl = sd + 2*PV_PSZ + 2*PV_VSZ; // 128

    const int tid = threadIdx.x;
    const int w = tid >> 5, t = tid & 31;
    const int qt = blockIdx.x, head = blockIdx.y, b = blockIdx.z;
    const int wq = (w & 3) * 32, wd = (w >> 2) * 32;

    const uint32_t pbase = (uint32_t)__cvta_generic_to_shared(Ps);
    const uint32_t vbase = (uint32_t)__cvta_generic_to_shared(Vs);

    float* pb = P + ((size_t)(b*NH + head)*NS + (size_t)qt*128) * NS;

    auto issue = [&](int kt, int buf) {
        #pragma unroll
        for (int i = 0; i < 8; i++) {
            int v = tid + i*256;
            int r = v >> 4, c = (v & 15)*4;
            cp16(pbase + (buf*PV_PSZ + r*PV_PP + c)*4,
                 pb + (size_t)r*NS + kt*64 + c);
        }
        const float* Vg = g_V + (size_t)(b*NS + kt*64) * NDK;
        #pragma unroll
        for (int i = 0; i < 4; i++) {
            int v = tid + i*256;
            int r = v >> 4, c = (v & 15)*4;
            cp16(vbase + (buf*PV_VSZ + r*PV_VP + c)*4, Vg + (size_t)r*NDK + c);
        }
    };

    issue(0, 0); CP_COMMIT();
    if (tid < 128) {
        int gq = (b*NH + head)*NS + qt*128 + tid;
        sl[tid] = 1.0f / g_L[gq];
    }

    float acc[2][4][4];
    #pragma unroll
    for (int i = 0; i < 2; i++)
        #pragma unroll
        for (int j = 0; j < 4; j++)
            #pragma unroll
            for (int r = 0; r < 4; r++) acc[i][j][r] = 0.f;

    for (int kt = 0; kt < 32; kt++) {
        int buf = kt & 1;
        if (kt + 1 < 32) issue(kt + 1, buf ^ 1);
        CP_COMMIT();
        CP_WAIT1();
        __syncthreads();
        const float* Pf = Ps + buf*PV_PSZ;
        const float* Vf = Vs + buf*PV_VSZ;

        // side-channel: p = u * (1/L), streaming store only
        #pragma unroll
        for (int i = 0; i < 8; i++) {
            int v = tid + i*256;
            int r = v >> 4, c = (v & 15)*4;
            float4 s = *(const float4*)&Pf[r*PV_PP + c];
            float il = sl[r];
            stcs4(pb + (size_t)r*NS + kt*64 + c,
                  make_float4(s.x*il, s.y*il, s.z*il, s.w*il));
        }

        // single MMA: U~ x V~ (both already tf32 bit patterns)
        #pragma unroll
        for (int ks = 0; ks < 8; ks++) {
            int kk = ks * 8;
            uint32_t af[2][4], bf[4][2];
            #pragma unroll
            for (int i = 0; i < 2; i++) {
                int o = (wq + i*16 + (t >> 2))*PV_PP + kk + (t & 3);
                af[i][0] = __float_as_uint(Pf[o]);
                af[i][1] = __float_as_uint(Pf[o + 8*PV_PP]);
                af[i][2] = __float_as_uint(Pf[o + 4]);
                af[i][3] = __float_as_uint(Pf[o + 8*PV_PP + 4]);
            }
            #pragma unroll
            for (int j = 0; j < 4; j++) {
                int o = (kk + (t & 3))*PV_VP + wd + j*8 + (t >> 2);
                bf[j][0] = __float_as_uint(Vf[o]);
                bf[j][1] = __float_as_uint(Vf[o + 4*PV_VP]);
            }
            #pragma unroll
            for (int i = 0; i < 2; i++)
                #pragma unroll
                for (int j = 0; j < 4; j++)
                    mma_tf32(acc[i][j], af[i], bf[j]);
        }
        __syncthreads();
    }

    // epilogue: X = acc / L
    #pragma unroll
    for (int i = 0; i < 2; i++) {
        int lr = wq + i*16 + (t >> 2);
        float il0 = sl[lr], il1 = sl[lr + 8];
        int row = qt*128 + lr;
        #pragma unroll
        for (int j = 0; j < 4; j++) {
            int col = head*NDK + wd + j*8 + (t & 3)*2;
            *(float2*)&g_X[(size_t)(b*NS + row)*NDM + col] =
                make_float2(acc[i][j][0]*il0, acc[i][j][1]*il0);
            *(float2*)&g_X[(size_t)(b*NS + row + 8)*NDM + col] =
                make_float2(acc[i][j][2]*il1, acc[i][j][3]*il1);
        }
    }
}

// ---------------------------------------------------------------------------
extern "C" void kernel_launch(void* const* d_in, const int* in_sizes, int n_in,
                              void* d_out, int out_size)
{
    const float* query = (const float*)d_in[0];
    const float* key_i = (const float*)d_in[1];
    const float* value = (const float*)d_in[2];
    const float* qW = (const float*)d_in[3];
    const float* qb = (const float*)d_in[4];
    const float* kW = (const float*)d_in[5];
    const float* kb = (const float*)d_in[6];
    const float* vW = (const float*)d_in[7];
    const float* vb = (const float*)d_in[8];
    const float* oW = (const float*)d_in[9];
    const float* ob = (const float*)d_in[10];

    float* out   = (float*)d_out;                    // [B,S,D_MODEL]
    float* pattn = out + (size_t)NB * NS * NDM;      // [B,H,S,S]

    float *pQ, *pK, *pV, *pX;
    cudaGetSymbolAddress((void**)&pQ, g_Q);
    cudaGetSymbolAddress((void**)&pK, g_K);
    cudaGetSymbolAddress((void**)&pV, g_V);
    cudaGetSymbolAddress((void**)&pX, g_X);

    cudaFuncSetAttribute(attn_scores_mma,
                         cudaFuncAttributeMaxDynamicSharedMemorySize, SC_SMEM);
    cudaFuncSetAttribute(attn_pv_mma,
                         cudaFuncAttributeMaxDynamicSharedMemorySize, PV_SMEM);

    dim3 gG(NDM/128, NROWS/128);     // (8, 32)
    dim3 gA(NS/128, NH, NB);         // (16, 16, 2)

    // 1) Q projection (2xTF32), d-permuted + tf32-rounded output
    proj_mma<1><<<gG, 256>>>(query, qW, qb, pQ, NROWS, NDM, NDM);
    // 2) K projection (2xTF32), d-permuted + tf32-rounded output
    projn64_mma<1><<<NROWS/64, 256>>>(key_i, kW, kb, pK, NROWS, NDM);
    // 3) V projection (2xTF32), tf32-rounded output (canonical)
    projn64_mma<0><<<NROWS/64, 256>>>(value, vW, vb, pV, NROWS, NDM);
    // 4) u = tf32(exp(scores)) + row sums (128-row tiles, .cg u store)
    attn_scores_mma<<<gA, 256, SC_SMEM>>>(pattn);
    // 5) X = (U @ V)/L (single MMA), p = u/L streamed out
    attn_pv_mma<<<gA, 256, PV_SMEM>>>(pattn);
    // 6) output projection (2xTF32)
    proj_mma<0><<<gG, 256>>>(pX, oW, ob, out, NROWS, NDM, NDM);
}

// round 16
// speedup vs baseline: 1.1986x; 1.1266x over previous
#include <cuda_runtime.h>
#include <math.h>
#include <stdint.h>

#define NB 2
#define NS 2048
#define NH 16
#define NDK 64
#define NDM 1024
#define NROWS (NB*NS)   // 4096

// Scratch (no allocs allowed)
__device__ float g_Q[(size_t)NROWS*NDM];   // d-permuted per head slice, tf32-rounded
__device__ float g_K[(size_t)NROWS*NDK];   // d-permuted, tf32-rounded
__device__ float g_V[(size_t)NROWS*NDK];   // canonical, tf32-rounded
__device__ float g_X[(size_t)NROWS*NDM];   // canonical
__device__ float g_L[NB*NH*NS];

// ===========================================================================
// helpers
// ===========================================================================
__device__ __forceinline__ void mma_tf32(float (&d)[4], const uint32_t (&a)[4],
                                         const uint32_t (&b)[2]) {
    asm volatile("mma.sync.aligned.m16n8k8.row.col.f32.tf32.tf32.f32 "
        "{%0,%1,%2,%3}, {%4,%5,%6,%7}, {%8,%9}, {%0,%1,%2,%3};"
        : "+f"(d[0]), "+f"(d[1]), "+f"(d[2]), "+f"(d[3])
        : "r"(a[0]), "r"(a[1]), "r"(a[2]), "r"(a[3]), "r"(b[0]), "r"(b[1]));
}
__device__ __forceinline__ float tf32_hi(float x) {
    uint32_t h;
    asm("cvt.rna.tf32.f32 %0, %1;" : "=r"(h) : "f"(x));
    return __uint_as_float(h);
}
__device__ __forceinline__ uint32_t tf32_bits(float x) {
    uint32_t h;
    asm("cvt.rna.tf32.f32 %0, %1;" : "=r"(h) : "f"(x));
    return h;
}
__device__ __forceinline__ void split1(float x, uint32_t& h, uint32_t& l) {
    float hf = tf32_hi(x);
    h = __float_as_uint(hf);
    l = __float_as_uint(x - hf);
}
__device__ __forceinline__ void cp16(uint32_t dst, const void* src) {
    asm volatile("cp.async.cg.shared.global [%0], [%1], 16;"
                 :: "r"(dst), "l"(src));
}
#define CP_COMMIT() asm volatile("cp.async.commit_group;" ::: "memory")
#define CP_WAIT1()  asm volatile("cp.async.wait_group 1;" ::: "memory")

// u store: .cg
__device__ __forceinline__ void stcg2(float* p, float a, float b) {
    asm volatile("st.global.cg.v2.f32 [%0], {%1, %2};" :: "l"(p), "f"(a), "f"(b)
                 : "memory");
}
// p store: .cs (write-once stream)
__device__ __forceinline__ void stcs4(float* p, float4 v) {
    asm volatile("st.global.cs.v4.f32 [%0], {%1, %2, %3, %4};"
                 :: "l"(p), "f"(v.x), "f"(v.y), "f"(v.z), "f"(v.w) : "memory");
}

// ===========================================================================
// Projection GEMM (1xTF32): C[M,N] = A[M,K] @ W[K,N] + bias, N % 128 == 0
// A and W both rounded to tf32 at fragment load (single MMA, no split ALU).
// PERM (Q-projection): output d -> 16*(d%4) + d/4 per 64-slice, tf32-ROUNDED.
// ===========================================================================
#define PJ_PA 20
#define PJ_PB 136
#define PJ_ASZ (128*PJ_PA)
#define PJ_BSZ (16*PJ_PB)

template<int PERM>
__global__ __launch_bounds__(256) void proj_mma(
    const float* __restrict__ A, const float* __restrict__ W,
    const float* __restrict__ bias, float* __restrict__ C,
    int M, int N, int K)
{
    __shared__ float As[2*PJ_ASZ];
    __shared__ float Bs[2*PJ_BSZ];
    const int tid = threadIdx.x;
    const int w = tid >> 5, t = tid & 31;
    const int m0 = blockIdx.y * 128, n0 = blockIdx.x * 128;
    const int wm = (w & 1) * 64, wn = (w >> 1) * 32;
    const int NC = K / 16;

    const float* Ab = A + (size_t)m0 * K;
    const float* Wb = W + n0;
    const uint32_t abase = (uint32_t)__cvta_generic_to_shared(As);
    const uint32_t bbase = (uint32_t)__cvta_generic_to_shared(Bs);

    auto issue = [&](int c, int buf) {
        #pragma unroll
        for (int i = 0; i < 2; i++) {
            int v = tid + i*256;
            int r = v >> 2, ca = (v & 3)*4;
            cp16(abase + (buf*PJ_ASZ + r*PJ_PA + ca)*4,
                 Ab + (size_t)r*K + c*16 + ca);
            int kr = v >> 5, cb = (v & 31)*4;
            cp16(bbase + (buf*PJ_BSZ + kr*PJ_PB + cb)*4,
                 Wb + (size_t)(c*16 + kr)*N + cb);
        }
    };

    float acc[4][4][4];
    #pragma unroll
    for (int i = 0; i < 4; i++)
        #pragma unroll
        for (int j = 0; j < 4; j++)
            #pragma unroll
            for (int r = 0; r < 4; r++) acc[i][j][r] = 0.f;

    issue(0, 0); CP_COMMIT();

    for (int c = 0; c < NC; c++) {
        int buf = c & 1;
        if (c + 1 < NC) issue(c + 1, buf ^ 1);
        CP_COMMIT();
        CP_WAIT1();
        __syncthreads();
        const float* Af = As + buf*PJ_ASZ;
        const float* Bf = Bs + buf*PJ_BSZ;
        #pragma unroll
        for (int ks = 0; ks < 2; ks++) {
            int kk = ks * 8;
            uint32_t af[4][4], bf[4][2];
            #pragma unroll
            for (int i = 0; i < 4; i++) {
                int o = (wm + i*16 + (t >> 2))*PJ_PA + kk + (t & 3);
                af[i][0] = tf32_bits(Af[o]);
                af[i][1] = tf32_bits(Af[o + 8*PJ_PA]);
                af[i][2] = tf32_bits(Af[o + 4]);
                af[i][3] = tf32_bits(Af[o + 8*PJ_PA + 4]);
            }
            #pragma unroll
            for (int j = 0; j < 4; j++) {
                int o = (kk + (t & 3))*PJ_PB + wn + j*8 + (t >> 2);
                bf[j][0] = tf32_bits(Bf[o]);
                bf[j][1] = tf32_bits(Bf[o + 4*PJ_PB]);
            }
            #pragma unroll
            for (int i = 0; i < 4; i++)
                #pragma unroll
                for (int j = 0; j < 4; j++)
                    mma_tf32(acc[i][j], af[i], bf[j]);
        }
        __syncthreads();
    }

    #pragma unroll
    for (int i = 0; i < 4; i++) {
        int r0 = m0 + wm + i*16 + (t >> 2);
        #pragma unroll
        for (int j = 0; j < 4; j++) {
            int col = n0 + wn + j*8 + (t & 3)*2;
            float2 bb = *(const float2*)&bias[col];
            float v00 = acc[i][j][0] + bb.x, v01 = acc[i][j][1] + bb.y;
            float v10 = acc[i][j][2] + bb.x, v11 = acc[i][j][3] + bb.y;
            if (PERM) {
                v00 = tf32_hi(v00); v01 = tf32_hi(v01);
                v10 = tf32_hi(v10); v11 = tf32_hi(v11);
                int d = col & 63, base = (col & ~63);
                int c0 = base + 16*(d & 3) + (d >> 2);
                C[(size_t)r0*N + c0]            = v00;
                C[(size_t)r0*N + c0 + 16]       = v01;
                C[(size_t)(r0 + 8)*N + c0]      = v10;
                C[(size_t)(r0 + 8)*N + c0 + 16] = v11;
            } else {
                *(float2*)&C[(size_t)r0*N + col]       = make_float2(v00, v01);
                *(float2*)&C[(size_t)(r0 + 8)*N + col] = make_float2(v10, v11);
            }
        }
    }
}

// ===========================================================================
// N=64 projection (2xTF32), tf32-ROUNDED outputs; PERM=1 applies in-row
// d-permutation 16*(d%4)+d/4 (K path); PERM=0 canonical (V path).
// ===========================================================================
#define P6_PA 20
#define P6_PB 72
#define P6_ASZ (64*P6_PA)
#define P6_BSZ (16*P6_PB)

template<int PERM>
__global__ __launch_bounds__(256) void projn64_mma(
    const float* __restrict__ A, const float* __restrict__ W,
    const float* __restrict__ bias, float* __restrict__ C,
    int M, int K)
{
    __shared__ float As[2*P6_ASZ];
    __shared__ float Bs[2*P6_BSZ];
    const int tid = threadIdx.x;
    const int w = tid >> 5, t = tid & 31;
    const int m0 = blockIdx.x * 64;
    const int wm = (w & 1) * 32, wn = (w >> 1) * 16;
    const int NC = K / 16;

    const float* Ab = A + (size_t)m0 * K;
    const uint32_t abase = (uint32_t)__cvta_generic_to_shared(As);
    const uint32_t bbase = (uint32_t)__cvta_generic_to_shared(Bs);

    auto issue = [&](int c, int buf) {
        int r = tid >> 2, ca = (tid & 3)*4;
        cp16(abase + (buf*P6_ASZ + r*P6_PA + ca)*4, Ab + (size_t)r*K + c*16 + ca);
        int kr = tid >> 4, cb = (tid & 15)*4;
        cp16(bbase + (buf*P6_BSZ + kr*P6_PB + cb)*4,
             W + (size_t)(c*16 + kr)*64 + cb);
    };

    float acc[2][2][4];
    #pragma unroll
    for (int i = 0; i < 2; i++)
        #pragma unroll
        for (int j = 0; j < 2; j++)
            #pragma unroll
            for (int r = 0; r < 4; r++) acc[i][j][r] = 0.f;

    issue(0, 0); CP_COMMIT();

    for (int c = 0; c < NC; c++) {
        int buf = c & 1;
        if (c + 1 < NC) issue(c + 1, buf ^ 1);
        CP_COMMIT();
        CP_WAIT1();
        __syncthreads();
        const float* Af = As + buf*P6_ASZ;
        const float* Bf = Bs + buf*P6_BSZ;
        #pragma unroll
        for (int ks = 0; ks < 2; ks++) {
            int kk = ks * 8;
            uint32_t afh[2][4], afl[2][4], bf[2][2];
            #pragma unroll
            for (int i = 0; i < 2; i++) {
                int o = (wm + i*16 + (t >> 2))*P6_PA + kk + (t & 3);
                split1(Af[o],              afh[i][0], afl[i][0]);
                split1(Af[o + 8*P6_PA],    afh[i][1], afl[i][1]);
                split1(Af[o + 4],          afh[i][2], afl[i][2]);
                split1(Af[o + 8*P6_PA + 4],afh[i][3], afl[i][3]);
            }
            #pragma unroll
            for (int j = 0; j < 2; j++) {
                int o = (kk + (t & 3))*P6_PB + wn + j*8 + (t >> 2);
                bf[j][0] = tf32_bits(Bf[o]);
                bf[j][1] = tf32_bits(Bf[o + 4*P6_PB]);
            }
            #pragma unroll
            for (int i = 0; i < 2; i++)
                #pragma unroll
                for (int j = 0; j < 2; j++) {
                    mma_tf32(acc[i][j], afh[i], bf[j]);
                    mma_tf32(acc[i][j], afl[i], bf[j]);
                }
        }
        __syncthreads();
    }

    #pragma unroll
    for (int i = 0; i < 2; i++) {
        int r0 = m0 + wm + i*16 + (t >> 2);
        #pragma unroll
        for (int j = 0; j < 2; j++) {
            int col = wn + j*8 + (t & 3)*2;
            float2 bb = *(const float2*)&bias[col];
            float v00 = tf32_hi(acc[i][j][0] + bb.x);
            float v01 = tf32_hi(acc[i][j][1] + bb.y);
            float v10 = tf32_hi(acc[i][j][2] + bb.x);
            float v11 = tf32_hi(acc[i][j][3] + bb.y);
            if (PERM) {
                int c0 = 16*(col & 3) + (col >> 2);
                C[(size_t)r0*64 + c0]            = v00;
                C[(size_t)r0*64 + c0 + 16]       = v01;
                C[(size_t)(r0 + 8)*64 + c0]      = v10;
                C[(size_t)(r0 + 8)*64 + c0 + 16] = v11;
            } else {
                *(float2*)&C[(size_t)r0*64 + col]       = make_float2(v00, v01);
                *(float2*)&C[(size_t)(r0 + 8)*64 + col] = make_float2(v10, v11);
            }
        }
    }
}

// ===========================================================================
// Pass A (1 MMA): u = tf32(exp((Q~ @ K~^T)*scale)) -> p_attn (.cg store);
// row sums -> g_L. 128-row q tiles, 2 CTAs/SM.
// ===========================================================================
#define SC_QP 76
#define SC_QSZ (128*SC_QP)
#define SC_KSZ (64*SC_QP)
#define SC_SMEM ((SC_QSZ + 2*SC_KSZ) * 4)

__global__ __launch_bounds__(256, 2) void attn_scores_mma(float* __restrict__ P)
{
    extern __shared__ float sd[];
    float* Qs = sd;                  // 128 x pitch76 (tf32, permuted)
    float* Ks = sd + SC_QSZ;         // 2 x 64 x pitch76 (tf32, permuted)

    const int tid = threadIdx.x;
    const int w = tid >> 5, t = tid & 31;
    const int tq = t & 3, tr = t >> 2;
    const int qt = blockIdx.x, head = blockIdx.y, b = blockIdx.z;
    const int wq = (w & 3) * 32, wn = (w >> 2) * 32;

    const uint32_t qbase = (uint32_t)__cvta_generic_to_shared(Qs);
    const uint32_t kbase = (uint32_t)__cvta_generic_to_shared(Ks);

    {
        const float* Qg = g_Q + (size_t)(b*NS + qt*128) * NDM + head*NDK;
        #pragma unroll
        for (int i = 0; i < 8; i++) {
            int v = tid + i*256;
            int r = v >> 4, m = v & 15;
            cp16(qbase + (r*SC_QP + 20*(m >> 2) + 4*(m & 3))*4,
                 Qg + (size_t)r*NDM + m*4);
        }
    }
    CP_COMMIT();
    auto issueK = [&](int kt, int buf) {
        const float* Kg = g_K + (size_t)(b*NS + kt*64) * NDK;
        #pragma unroll
        for (int i = 0; i < 4; i++) {
            int v = tid + i*256;
            int r = v >> 4, m = v & 15;
            cp16(kbase + (buf*SC_KSZ + r*SC_QP + 20*(m >> 2) + 4*(m & 3))*4,
                 Kg + (size_t)r*NDK + m*4);
        }
    };
    issueK(0, 0); CP_COMMIT();

    float lsum[2][2];
    #pragma unroll
    for (int i = 0; i < 2; i++)
        #pragma unroll
        for (int hf = 0; hf < 2; hf++) lsum[i][hf] = 0.f;

    float* pb = P + ((size_t)(b*NH + head)*NS + (size_t)qt*128) * NS;

    for (int kt = 0; kt < 32; kt++) {
        int buf = kt & 1;
        if (kt + 1 < 32) issueK(kt + 1, buf ^ 1);
        CP_COMMIT();
        CP_WAIT1();
        __syncthreads();
        const float* Kf = Ks + buf*SC_KSZ;

        float acc[2][4][4];
        #pragma unroll
        for (int i = 0; i < 2; i++)
            #pragma unroll
            for (int j = 0; j < 4; j++)
                #pragma unroll
                for (int r = 0; r < 4; r++) acc[i][j][r] = 0.f;

        #pragma unroll
        for (int ksb = 0; ksb < 4; ksb++) {
            float4 qr0[2], qr1[2], kb[4];
            #pragma unroll
            for (int i = 0; i < 2; i++) {
                int r = wq + i*16 + tr;
                qr0[i] = *(const float4*)&Qs[r*SC_QP + 20*tq + 4*ksb];
                qr1[i] = *(const float4*)&Qs[(r + 8)*SC_QP + 20*tq + 4*ksb];
            }
            #pragma unroll
            for (int j = 0; j < 4; j++) {
                int n = wn + j*8 + tr;
                kb[j] = *(const float4*)&Kf[n*SC_QP + 20*tq + 4*ksb];
            }
            #pragma unroll
            for (int kss = 0; kss < 2; kss++) {
                uint32_t bf[4][2];
                #pragma unroll
                for (int j = 0; j < 4; j++) {
                    bf[j][0] = __float_as_uint(kss ? kb[j].z : kb[j].x);
                    bf[j][1] = __float_as_uint(kss ? kb[j].w : kb[j].y);
                }
                #pragma unroll
                for (int i = 0; i < 2; i++) {
                    uint32_t af[4];
                    af[0] = __float_as_uint(kss ? qr0[i].z : qr0[i].x);
                    af[2] = __float_as_uint(kss ? qr0[i].w : qr0[i].y);
                    af[1] = __float_as_uint(kss ? qr1[i].z : qr1[i].x);
                    af[3] = __float_as_uint(kss ? qr1[i].w : qr1[i].y);
                    #pragma unroll
                    for (int j = 0; j < 4; j++)
                        mma_tf32(acc[i][j], af, bf[j]);
                }
            }
        }

        // epilogue: u = tf32(exp(s*scale)); .cg store; row sums
        #pragma unroll
        for (int i = 0; i < 2; i++) {
            #pragma unroll
            for (int hf = 0; hf < 2; hf++) {
                float vals[8];
                #pragma unroll
                for (int j = 0; j < 4; j++) {
                    vals[j*2+0] = tf32_hi(__expf(acc[i][j][hf*2+0] * 0.125f));
                    vals[j*2+1] = tf32_hi(__expf(acc[i][j][hf*2+1] * 0.125f));
                }
                float s = 0.f;
                #pragma unroll
                for (int e = 0; e < 8; e++) s += vals[e];
                lsum[i][hf] += s;

                int row = wq + i*16 + hf*8 + tr;
                float* rp = pb + (size_t)row*NS + kt*64 + wn + tq*2;
                #pragma unroll
                for (int j = 0; j < 4; j++)
                    stcg2(rp + j*8, vals[j*2], vals[j*2+1]);
            }
        }
        __syncthreads();
    }

    // reduce sums: quad lanes, then 2 n-warps (red aliases Ks, K dead now)
    float* red = Ks;
    #pragma unroll
    for (int i = 0; i < 2; i++)
        #pragma unroll
        for (int hf = 0; hf < 2; hf++) {
            float l = lsum[i][hf];
            l += __shfl_xor_sync(0xffffffffu, l, 1);
            l += __shfl_xor_sync(0xffffffffu, l, 2);
            if (tq == 0) {
                int row = wq + i*16 + hf*8 + tr;
                red[row*2 + (w >> 2)] = l;
            }
        }
    __syncthreads();
    if (tid < 128) {
        int gq = (b*NH + head)*NS + qt*128 + tid;
        g_L[gq] = red[tid*2] + red[tid*2+1];
    }
}

// ===========================================================================
// Pass B (1 MMA): X = (U~ @ V~) / L; p = u/L streamed out.
// ===========================================================================
#define PV_PP 68
#define PV_VP 72
#define PV_PSZ (128*PV_PP)
#define PV_VSZ (64*PV_VP)
#define PV_SMEM ((2*PV_PSZ + 2*PV_VSZ + 256) * 4)

__global__ __launch_bounds__(256) void attn_pv_mma(float* __restrict__ P)
{
    extern __shared__ float sd[];
    float* Ps = sd;                       // 2 x 128*68
    float* Vs = sd + 2*PV_PSZ;            // 2 x 64*72
    float* sl = sd + 2*PV_PSZ + 2*PV_VSZ; // 128

    const int tid = threadIdx.x;
    const int w = tid >> 5, t = tid & 31;
    const int qt = blockIdx.x, head = blockIdx.y, b = blockIdx.z;
    const int wq = (w & 3) * 32, wd = (w >> 2) * 32;

    const uint32_t pbase = (uint32_t)__cvta_generic_to_shared(Ps);
    const uint32_t vbase = (uint32_t)__cvta_generic_to_shared(Vs);

    float* pb = P + ((size_t)(b*NH + head)*NS + (size_t)qt*128) * NS;

    auto issue = [&](int kt, int buf) {
        #pragma unroll
        for (int i = 0; i < 8; i++) {
            int v = tid + i*256;
            int r = v >> 4, c = (v & 15)*4;
            cp16(pbase + (buf*PV_PSZ + r*PV_PP + c)*4,
                 pb + (size_t)r*NS + kt*64 + c);
        }
        const float* Vg = g_V + (size_t)(b*NS + kt*64) * NDK;
        #pragma unroll
        for (int i = 0; i < 4; i++) {
            int v = tid + i*256;
            int r = v >> 4, c = (v & 15)*4;
            cp16(vbase + (buf*PV_VSZ + r*PV_VP + c)*4, Vg + (size_t)r*NDK + c);
        }
    };

    issue(0, 0); CP_COMMIT();
    if (tid < 128) {
        int gq = (b*NH + head)*NS + qt*128 + tid;
        sl[tid] = 1.0f / g_L[gq];
    }

    float acc[2][4][4];
    #pragma unroll
    for (int i = 0; i < 2; i++)
        #pragma unroll
        for (int j = 0; j < 4; j++)
            #pragma unroll
            for (int r = 0; r < 4; r++) acc[i][j][r] = 0.f;

    for (int kt = 0; kt < 32; kt++) {
        int buf = kt & 1;
        if (kt + 1 < 32) issue(kt + 1, buf ^ 1);
        CP_COMMIT();
        CP_WAIT1();
        __syncthreads();
        const float* Pf = Ps + buf*PV_PSZ;
        const float* Vf = Vs + buf*PV_VSZ;

        // side-channel: p = u * (1/L), streaming store only
        #pragma unroll
        for (int i = 0; i < 8; i++) {
            int v = tid + i*256;
            int r = v >> 4, c = (v & 15)*4;
            float4 s = *(const float4*)&Pf[r*PV_PP + c];
            float il = sl[r];
            stcs4(pb + (size_t)r*NS + kt*64 + c,
                  make_float4(s.x*il, s.y*il, s.z*il, s.w*il));
        }

        // single MMA: U~ x V~ (both already tf32 bit patterns)
        #pragma unroll
        for (int ks = 0; ks < 8; ks++) {
            int kk = ks * 8;
            uint32_t af[2][4], bf[4][2];
            #pragma unroll
            for (int i = 0; i < 2; i++) {
                int o = (wq + i*16 + (t >> 2))*PV_PP + kk + (t & 3);
                af[i][0] = __float_as_uint(Pf[o]);
                af[i][1] = __float_as_uint(Pf[o + 8*PV_PP]);
                af[i][2] = __float_as_uint(Pf[o + 4]);
                af[i][3] = __float_as_uint(Pf[o + 8*PV_PP + 4]);
            }
            #pragma unroll
            for (int j = 0; j < 4; j++) {
                int o = (kk + (t & 3))*PV_VP + wd + j*8 + (t >> 2);
                bf[j][0] = __float_as_uint(Vf[o]);
                bf[j][1] = __float_as_uint(Vf[o + 4*PV_VP]);
            }
            #pragma unroll
            for (int i = 0; i < 2; i++)
                #pragma unroll
                for (int j = 0; j < 4; j++)
                    mma_tf32(acc[i][j], af[i], bf[j]);
        }
        __syncthreads();
    }

    // epilogue: X = acc / L
    #pragma unroll
    for (int i = 0; i < 2; i++) {
        int lr = wq + i*16 + (t >> 2);
        float il0 = sl[lr], il1 = sl[lr + 8];
        int row = qt*128 + lr;
        #pragma unroll
        for (int j = 0; j < 4; j++) {
            int col = head*NDK + wd + j*8 + (t & 3)*2;
            *(float2*)&g_X[(size_t)(b*NS + row)*NDM + col] =
                make_float2(acc[i][j][0]*il0, acc[i][j][1]*il0);
            *(float2*)&g_X[(size_t)(b*NS + row + 8)*NDM + col] =
                make_float2(acc[i][j][2]*il1, acc[i][j][3]*il1);
        }
    }
}

// ---------------------------------------------------------------------------
extern "C" void kernel_launch(void* const* d_in, const int* in_sizes, int n_in,
                              void* d_out, int out_size)
{
    const float* query = (const float*)d_in[0];
    const float* key_i = (const float*)d_in[1];
    const float* value = (const float*)d_in[2];
    const float* qW = (const float*)d_in[3];
    const float* qb = (const float*)d_in[4];
    const float* kW = (const float*)d_in[5];
    const float* kb = (const float*)d_in[6];
    const float* vW = (const float*)d_in[7];
    const float* vb = (const float*)d_in[8];
    const float* oW = (const float*)d_in[9];
    const float* ob = (const float*)d_in[10];

    float* out   = (float*)d_out;                    // [B,S,D_MODEL]
    float* pattn = out + (size_t)NB * NS * NDM;      // [B,H,S,S]

    float *pQ, *pK, *pV, *pX;
    cudaGetSymbolAddress((void**)&pQ, g_Q);
    cudaGetSymbolAddress((void**)&pK, g_K);
    cudaGetSymbolAddress((void**)&pV, g_V);
    cudaGetSymbolAddress((void**)&pX, g_X);

    cudaFuncSetAttribute(attn_scores_mma,
                         cudaFuncAttributeMaxDynamicSharedMemorySize, SC_SMEM);
    cudaFuncSetAttribute(attn_pv_mma,
                         cudaFuncAttributeMaxDynamicSharedMemorySize, PV_SMEM);

    dim3 gG(NDM/128, NROWS/128);     // (8, 32)
    dim3 gA(NS/128, NH, NB);         // (16, 16, 2)

    // 1) Q projection (1xTF32), d-permuted + tf32-rounded output
    proj_mma<1><<<gG, 256>>>(query, qW, qb, pQ, NROWS, NDM, NDM);
    // 2) K projection (2xTF32), d-permuted + tf32-rounded output
    projn64_mma<1><<<NROWS/64, 256>>>(key_i, kW, kb, pK, NROWS, NDM);
    // 3) V projection (2xTF32), tf32-rounded output (canonical)
    projn64_mma<0><<<NROWS/64, 256>>>(value, vW, vb, pV, NROWS, NDM);
    // 4) u = tf32(exp(scores)) + row sums
    attn_scores_mma<<<gA, 256, SC_SMEM>>>(pattn);
    // 5) X = (U @ V)/L (single MMA), p = u/L streamed out
    attn_pv_mma<<<gA, 256, PV_SMEM>>>(pattn);
    // 6) output projection (1xTF32)
    proj_mma<0><<<gG, 256>>>(pX, oW, ob, out, NROWS, NDM, NDM);
}

// round 17
// speedup vs baseline: 1.2645x; 1.0550x over previous
#include <cuda_runtime.h>
#include <math.h>
#include <stdint.h>

#define NB 2
#define NS 2048
#define NH 16
#define NDK 64
#define NDM 1024
#define NROWS (NB*NS)   // 4096

// Scratch (no allocs allowed)
__device__ float g_Q[(size_t)NROWS*NDM];   // d-permuted per head slice, tf32-rounded
__device__ float g_K[(size_t)NROWS*NDK];   // d-permuted, tf32-rounded
__device__ float g_V[(size_t)NROWS*NDK];   // canonical, tf32-rounded
__device__ float g_X[(size_t)NROWS*NDM];   // canonical
__device__ float g_L[NB*NH*NS];

// ===========================================================================
// helpers
// ===========================================================================
__device__ __forceinline__ void mma_tf32(float (&d)[4], const uint32_t (&a)[4],
                                         const uint32_t (&b)[2]) {
    asm volatile("mma.sync.aligned.m16n8k8.row.col.f32.tf32.tf32.f32 "
        "{%0,%1,%2,%3}, {%4,%5,%6,%7}, {%8,%9}, {%0,%1,%2,%3};"
        : "+f"(d[0]), "+f"(d[1]), "+f"(d[2]), "+f"(d[3])
        : "r"(a[0]), "r"(a[1]), "r"(a[2]), "r"(a[3]), "r"(b[0]), "r"(b[1]));
}
__device__ __forceinline__ float tf32_hi(float x) {
    uint32_t h;
    asm("cvt.rna.tf32.f32 %0, %1;" : "=r"(h) : "f"(x));
    return __uint_as_float(h);
}
__device__ __forceinline__ uint32_t tf32_bits(float x) {
    uint32_t h;
    asm("cvt.rna.tf32.f32 %0, %1;" : "=r"(h) : "f"(x));
    return h;
}
__device__ __forceinline__ void split1(float x, uint32_t& h, uint32_t& l) {
    float hf = tf32_hi(x);
    h = __float_as_uint(hf);
    l = __float_as_uint(x - hf);
}
__device__ __forceinline__ void cp16(uint32_t dst, const void* src) {
    asm volatile("cp.async.cg.shared.global [%0], [%1], 16;"
                 :: "r"(dst), "l"(src));
}
#define CP_COMMIT() asm volatile("cp.async.commit_group;" ::: "memory")
#define CP_WAIT1()  asm volatile("cp.async.wait_group 1;" ::: "memory")

// u store: .cg
__device__ __forceinline__ void stcg2(float* p, float a, float b) {
    asm volatile("st.global.cg.v2.f32 [%0], {%1, %2};" :: "l"(p), "f"(a), "f"(b)
                 : "memory");
}
// p store: .cs (write-once stream)
__device__ __forceinline__ void stcs4(float* p, float4 v) {
    asm volatile("st.global.cs.v4.f32 [%0], {%1, %2, %3, %4};"
                 :: "l"(p), "f"(v.x), "f"(v.y), "f"(v.z), "f"(v.w) : "memory");
}

// ===========================================================================
// Projection GEMM (1xTF32): C[M,N] = A[M,K] @ W[K,N] + bias, N % 128 == 0
// A and W both rounded to tf32 at fragment load (single MMA, no split ALU).
// PERM (Q-projection): output d -> 16*(d%4) + d/4 per 64-slice, tf32-ROUNDED.
// ===========================================================================
#define PJ_PA 20
#define PJ_PB 136
#define PJ_ASZ (128*PJ_PA)
#define PJ_BSZ (16*PJ_PB)

template<int PERM>
__global__ __launch_bounds__(256) void proj_mma(
    const float* __restrict__ A, const float* __restrict__ W,
    const float* __restrict__ bias, float* __restrict__ C,
    int M, int N, int K)
{
    __shared__ float As[2*PJ_ASZ];
    __shared__ float Bs[2*PJ_BSZ];
    const int tid = threadIdx.x;
    const int w = tid >> 5, t = tid & 31;
    const int m0 = blockIdx.y * 128, n0 = blockIdx.x * 128;
    const int wm = (w & 1) * 64, wn = (w >> 1) * 32;
    const int NC = K / 16;

    const float* Ab = A + (size_t)m0 * K;
    const float* Wb = W + n0;
    const uint32_t abase = (uint32_t)__cvta_generic_to_shared(As);
    const uint32_t bbase = (uint32_t)__cvta_generic_to_shared(Bs);

    auto issue = [&](int c, int buf) {
        #pragma unroll
        for (int i = 0; i < 2; i++) {
            int v = tid + i*256;
            int r = v >> 2, ca = (v & 3)*4;
            cp16(abase + (buf*PJ_ASZ + r*PJ_PA + ca)*4,
                 Ab + (size_t)r*K + c*16 + ca);
            int kr = v >> 5, cb = (v & 31)*4;
            cp16(bbase + (buf*PJ_BSZ + kr*PJ_PB + cb)*4,
                 Wb + (size_t)(c*16 + kr)*N + cb);
        }
    };

    float acc[4][4][4];
    #pragma unroll
    for (int i = 0; i < 4; i++)
        #pragma unroll
        for (int j = 0; j < 4; j++)
            #pragma unroll
            for (int r = 0; r < 4; r++) acc[i][j][r] = 0.f;

    issue(0, 0); CP_COMMIT();

    for (int c = 0; c < NC; c++) {
        int buf = c & 1;
        if (c + 1 < NC) issue(c + 1, buf ^ 1);
        CP_COMMIT();
        CP_WAIT1();
        __syncthreads();
        const float* Af = As + buf*PJ_ASZ;
        const float* Bf = Bs + buf*PJ_BSZ;
        #pragma unroll
        for (int ks = 0; ks < 2; ks++) {
            int kk = ks * 8;
            uint32_t af[4][4], bf[4][2];
            #pragma unroll
            for (int i = 0; i < 4; i++) {
                int o = (wm + i*16 + (t >> 2))*PJ_PA + kk + (t & 3);
                af[i][0] = tf32_bits(Af[o]);
                af[i][1] = tf32_bits(Af[o + 8*PJ_PA]);
                af[i][2] = tf32_bits(Af[o + 4]);
                af[i][3] = tf32_bits(Af[o + 8*PJ_PA + 4]);
            }
            #pragma unroll
            for (int j = 0; j < 4; j++) {
                int o = (kk + (t & 3))*PJ_PB + wn + j*8 + (t >> 2);
                bf[j][0] = tf32_bits(Bf[o]);
                bf[j][1] = tf32_bits(Bf[o + 4*PJ_PB]);
            }
            #pragma unroll
            for (int i = 0; i < 4; i++)
                #pragma unroll
                for (int j = 0; j < 4; j++)
                    mma_tf32(acc[i][j], af[i], bf[j]);
        }
        __syncthreads();
    }

    #pragma unroll
    for (int i = 0; i < 4; i++) {
        int r0 = m0 + wm + i*16 + (t >> 2);
        #pragma unroll
        for (int j = 0; j < 4; j++) {
            int col = n0 + wn + j*8 + (t & 3)*2;
            float2 bb = *(const float2*)&bias[col];
            float v00 = acc[i][j][0] + bb.x, v01 = acc[i][j][1] + bb.y;
            float v10 = acc[i][j][2] + bb.x, v11 = acc[i][j][3] + bb.y;
            if (PERM) {
                v00 = tf32_hi(v00); v01 = tf32_hi(v01);
                v10 = tf32_hi(v10); v11 = tf32_hi(v11);
                int d = col & 63, base = (col & ~63);
                int c0 = base + 16*(d & 3) + (d >> 2);
                C[(size_t)r0*N + c0]            = v00;
                C[(size_t)r0*N + c0 + 16]       = v01;
                C[(size_t)(r0 + 8)*N + c0]      = v10;
                C[(size_t)(r0 + 8)*N + c0 + 16] = v11;
            } else {
                *(float2*)&C[(size_t)r0*N + col]       = make_float2(v00, v01);
                *(float2*)&C[(size_t)(r0 + 8)*N + col] = make_float2(v10, v11);
            }
        }
    }
}

// ===========================================================================
// MERGED K+V projection (2xTF32), tf32-ROUNDED outputs.
// grid.y == 0: K path (d-permuted output);  grid.y == 1: V path (canonical).
// One launch, 128 CTAs — fills the SMs that two serial 64-CTA launches waste.
// ===========================================================================
#define P6_PA 20
#define P6_PB 72
#define P6_ASZ (64*P6_PA)
#define P6_BSZ (16*P6_PB)

__global__ __launch_bounds__(256) void kvproj_mma(
    const float* __restrict__ Akey, const float* __restrict__ Aval,
    const float* __restrict__ kW, const float* __restrict__ kb,
    const float* __restrict__ vW, const float* __restrict__ vb,
    float* __restrict__ Ck, float* __restrict__ Cv, int M, int K)
{
    __shared__ float As[2*P6_ASZ];
    __shared__ float Bs[2*P6_BSZ];
    const int tid = threadIdx.x;
    const int w = tid >> 5, t = tid & 31;
    const int m0 = blockIdx.x * 64;
    const int isV = blockIdx.y;          // 0 = K path, 1 = V path
    const int wm = (w & 1) * 32, wn = (w >> 1) * 16;
    const int NC = K / 16;

    const float* A    = isV ? Aval : Akey;
    const float* W    = isV ? vW : kW;
    const float* bias = isV ? vb : kb;
    float*       C    = isV ? Cv : Ck;

    const float* Ab = A + (size_t)m0 * K;
    const uint32_t abase = (uint32_t)__cvta_generic_to_shared(As);
    const uint32_t bbase = (uint32_t)__cvta_generic_to_shared(Bs);

    auto issue = [&](int c, int buf) {
        int r = tid >> 2, ca = (tid & 3)*4;
        cp16(abase + (buf*P6_ASZ + r*P6_PA + ca)*4, Ab + (size_t)r*K + c*16 + ca);
        int kr = tid >> 4, cb = (tid & 15)*4;
        cp16(bbase + (buf*P6_BSZ + kr*P6_PB + cb)*4,
             W + (size_t)(c*16 + kr)*64 + cb);
    };

    float acc[2][2][4];
    #pragma unroll
    for (int i = 0; i < 2; i++)
        #pragma unroll
        for (int j = 0; j < 2; j++)
            #pragma unroll
            for (int r = 0; r < 4; r++) acc[i][j][r] = 0.f;

    issue(0, 0); CP_COMMIT();

    for (int c = 0; c < NC; c++) {
        int buf = c & 1;
        if (c + 1 < NC) issue(c + 1, buf ^ 1);
        CP_COMMIT();
        CP_WAIT1();
        __syncthreads();
        const float* Af = As + buf*P6_ASZ;
        const float* Bf = Bs + buf*P6_BSZ;
        #pragma unroll
        for (int ks = 0; ks < 2; ks++) {
            int kk = ks * 8;
            uint32_t afh[2][4], afl[2][4], bf[2][2];
            #pragma unroll
            for (int i = 0; i < 2; i++) {
                int o = (wm + i*16 + (t >> 2))*P6_PA + kk + (t & 3);
                split1(Af[o],              afh[i][0], afl[i][0]);
                split1(Af[o + 8*P6_PA],    afh[i][1], afl[i][1]);
                split1(Af[o + 4],          afh[i][2], afl[i][2]);
                split1(Af[o + 8*P6_PA + 4],afh[i][3], afl[i][3]);
            }
            #pragma unroll
            for (int j = 0; j < 2; j++) {
                int o = (kk + (t & 3))*P6_PB + wn + j*8 + (t >> 2);
                bf[j][0] = tf32_bits(Bf[o]);
                bf[j][1] = tf32_bits(Bf[o + 4*P6_PB]);
            }
            #pragma unroll
            for (int i = 0; i < 2; i++)
                #pragma unroll
                for (int j = 0; j < 2; j++) {
                    mma_tf32(acc[i][j], afh[i], bf[j]);
                    mma_tf32(acc[i][j], afl[i], bf[j]);
                }
        }
        __syncthreads();
    }

    #pragma unroll
    for (int i = 0; i < 2; i++) {
        int r0 = m0 + wm + i*16 + (t >> 2);
        #pragma unroll
        for (int j = 0; j < 2; j++) {
            int col = wn + j*8 + (t & 3)*2;
            float2 bb = *(const float2*)&bias[col];
            float v00 = tf32_hi(acc[i][j][0] + bb.x);
            float v01 = tf32_hi(acc[i][j][1] + bb.y);
            float v10 = tf32_hi(acc[i][j][2] + bb.x);
            float v11 = tf32_hi(acc[i][j][3] + bb.y);
            if (!isV) {
                int c0 = 16*(col & 3) + (col >> 2);
                C[(size_t)r0*64 + c0]            = v00;
                C[(size_t)r0*64 + c0 + 16]       = v01;
                C[(size_t)(r0 + 8)*64 + c0]      = v10;
                C[(size_t)(r0 + 8)*64 + c0 + 16] = v11;
            } else {
                *(float2*)&C[(size_t)r0*64 + col]       = make_float2(v00, v01);
                *(float2*)&C[(size_t)(r0 + 8)*64 + col] = make_float2(v10, v11);
            }
        }
    }
}

// ===========================================================================
// Pass A (1 MMA): u = tf32(exp((Q~ @ K~^T)*scale)) -> p_attn (.cg store);
// row sums -> g_L. 128-row q tiles, 2 CTAs/SM.
// ===========================================================================
#define SC_QP 76
#define SC_QSZ (128*SC_QP)
#define SC_KSZ (64*SC_QP)
#define SC_SMEM ((SC_QSZ + 2*SC_KSZ) * 4)

__global__ __launch_bounds__(256, 2) void attn_scores_mma(float* __restrict__ P)
{
    extern __shared__ float sd[];
    float* Qs = sd;                  // 128 x pitch76 (tf32, permuted)
    float* Ks = sd + SC_QSZ;         // 2 x 64 x pitch76 (tf32, permuted)

    const int tid = threadIdx.x;
    const int w = tid >> 5, t = tid & 31;
    const int tq = t & 3, tr = t >> 2;
    const int qt = blockIdx.x, head = blockIdx.y, b = blockIdx.z;
    const int wq = (w & 3) * 32, wn = (w >> 2) * 32;

    const uint32_t qbase = (uint32_t)__cvta_generic_to_shared(Qs);
    const uint32_t kbase = (uint32_t)__cvta_generic_to_shared(Ks);

    {
        const float* Qg = g_Q + (size_t)(b*NS + qt*128) * NDM + head*NDK;
        #pragma unroll
        for (int i = 0; i < 8; i++) {
            int v = tid + i*256;
            int r = v >> 4, m = v & 15;
            cp16(qbase + (r*SC_QP + 20*(m >> 2) + 4*(m & 3))*4,
                 Qg + (size_t)r*NDM + m*4);
        }
    }
    CP_COMMIT();
    auto issueK = [&](int kt, int buf) {
        const float* Kg = g_K + (size_t)(b*NS + kt*64) * NDK;
        #pragma unroll
        for (int i = 0; i < 4; i++) {
            int v = tid + i*256;
            int r = v >> 4, m = v & 15;
            cp16(kbase + (buf*SC_KSZ + r*SC_QP + 20*(m >> 2) + 4*(m & 3))*4,
                 Kg + (size_t)r*NDK + m*4);
        }
    };
    issueK(0, 0); CP_COMMIT();

    float lsum[2][2];
    #pragma unroll
    for (int i = 0; i < 2; i++)
        #pragma unroll
        for (int hf = 0; hf < 2; hf++) lsum[i][hf] = 0.f;

    float* pb = P + ((size_t)(b*NH + head)*NS + (size_t)qt*128) * NS;

    for (int kt = 0; kt < 32; kt++) {
        int buf = kt & 1;
        if (kt + 1 < 32) issueK(kt + 1, buf ^ 1);
        CP_COMMIT();
        CP_WAIT1();
        __syncthreads();
        const float* Kf = Ks + buf*SC_KSZ;

        float acc[2][4][4];
        #pragma unroll
        for (int i = 0; i < 2; i++)
            #pragma unroll
            for (int j = 0; j < 4; j++)
                #pragma unroll
                for (int r = 0; r < 4; r++) acc[i][j][r] = 0.f;

        #pragma unroll
        for (int ksb = 0; ksb < 4; ksb++) {
            float4 qr0[2], qr1[2], kb[4];
            #pragma unroll
            for (int i = 0; i < 2; i++) {
                int r = wq + i*16 + tr;
                qr0[i] = *(const float4*)&Qs[r*SC_QP + 20*tq + 4*ksb];
                qr1[i] = *(const float4*)&Qs[(r + 8)*SC_QP + 20*tq + 4*ksb];
            }
            #pragma unroll
            for (int j = 0; j < 4; j++) {
                int n = wn + j*8 + tr;
                kb[j] = *(const float4*)&Kf[n*SC_QP + 20*tq + 4*ksb];
            }
            #pragma unroll
            for (int kss = 0; kss < 2; kss++) {
                uint32_t bf[4][2];
                #pragma unroll
                for (int j = 0; j < 4; j++) {
                    bf[j][0] = __float_as_uint(kss ? kb[j].z : kb[j].x);
                    bf[j][1] = __float_as_uint(kss ? kb[j].w : kb[j].y);
                }
                #pragma unroll
                for (int i = 0; i < 2; i++) {
                    uint32_t af[4];
                    af[0] = __float_as_uint(kss ? qr0[i].z : qr0[i].x);
                    af[2] = __float_as_uint(kss ? qr0[i].w : qr0[i].y);
                    af[1] = __float_as_uint(kss ? qr1[i].z : qr1[i].x);
                    af[3] = __float_as_uint(kss ? qr1[i].w : qr1[i].y);
                    #pragma unroll
                    for (int j = 0; j < 4; j++)
                        mma_tf32(acc[i][j], af, bf[j]);
                }
            }
        }

        // epilogue: u = tf32(exp(s*scale)); .cg store; row sums
        #pragma unroll
        for (int i = 0; i < 2; i++) {
            #pragma unroll
            for (int hf = 0; hf < 2; hf++) {
                float vals[8];
                #pragma unroll
                for (int j = 0; j < 4; j++) {
                    vals[j*2+0] = tf32_hi(__expf(acc[i][j][hf*2+0] * 0.125f));
                    vals[j*2+1] = tf32_hi(__expf(acc[i][j][hf*2+1] * 0.125f));
                }
                float s = 0.f;
                #pragma unroll
                for (int e = 0; e < 8; e++) s += vals[e];
                lsum[i][hf] += s;

                int row = wq + i*16 + hf*8 + tr;
                float* rp = pb + (size_t)row*NS + kt*64 + wn + tq*2;
                #pragma unroll
                for (int j = 0; j < 4; j++)
                    stcg2(rp + j*8, vals[j*2], vals[j*2+1]);
            }
        }
        __syncthreads();
    }

    // reduce sums: quad lanes, then 2 n-warps (red aliases Ks, K dead now)
    float* red = Ks;
    #pragma unroll
    for (int i = 0; i < 2; i++)
        #pragma unroll
        for (int hf = 0; hf < 2; hf++) {
            float l = lsum[i][hf];
            l += __shfl_xor_sync(0xffffffffu, l, 1);
            l += __shfl_xor_sync(0xffffffffu, l, 2);
            if (tq == 0) {
                int row = wq + i*16 + hf*8 + tr;
                red[row*2 + (w >> 2)] = l;
            }
        }
    __syncthreads();
    if (tid < 128) {
        int gq = (b*NH + head)*NS + qt*128 + tid;
        g_L[gq] = red[tid*2] + red[tid*2+1];
    }
}

// ===========================================================================
// Pass B (1 MMA): X = (U~ @ V~) / L; p = u/L streamed out.
// ===========================================================================
#define PV_PP 68
#define PV_VP 72
#define PV_PSZ (128*PV_PP)
#define PV_VSZ (64*PV_VP)
#define PV_SMEM ((2*PV_PSZ + 2*PV_VSZ + 256) * 4)

__global__ __launch_bounds__(256) void attn_pv_mma(float* __restrict__ P)
{
    extern __shared__ float sd[];
    float* Ps = sd;                       // 2 x 128*68
    float* Vs = sd + 2*PV_PSZ;            // 2 x 64*72
    float* sl = sd + 2*PV_PSZ + 2*PV_VSZ; // 128

    const int tid = threadIdx.x;
    const int w = tid >> 5, t = tid & 31;
    const int qt = blockIdx.x, head = blockIdx.y, b = blockIdx.z;
    const int wq = (w & 3) * 32, wd = (w >> 2) * 32;

    const uint32_t pbase = (uint32_t)__cvta_generic_to_shared(Ps);
    const uint32_t vbase = (uint32_t)__cvta_generic_to_shared(Vs);

    float* pb = P + ((size_t)(b*NH + head)*NS + (size_t)qt*128) * NS;

    auto issue = [&](int kt, int buf) {
        #pragma unroll
        for (int i = 0; i < 8; i++) {
            int v = tid + i*256;
            int r = v >> 4, c = (v & 15)*4;
            cp16(pbase + (buf*PV_PSZ + r*PV_PP + c)*4,
                 pb + (size_t)r*NS + kt*64 + c);
        }
        const float* Vg = g_V + (size_t)(b*NS + kt*64) * NDK;
        #pragma unroll
        for (int i = 0; i < 4; i++) {
            int v = tid + i*256;
            int r = v >> 4, c = (v & 15)*4;
            cp16(vbase + (buf*PV_VSZ + r*PV_VP + c)*4, Vg + (size_t)r*NDK + c);
        }
    };

    issue(0, 0); CP_COMMIT();
    if (tid < 128) {
        int gq = (b*NH + head)*NS + qt*128 + tid;
        sl[tid] = 1.0f / g_L[gq];
    }

    float acc[2][4][4];
    #pragma unroll
    for (int i = 0; i < 2; i++)
        #pragma unroll
        for (int j = 0; j < 4; j++)
            #pragma unroll
            for (int r = 0; r < 4; r++) acc[i][j][r] = 0.f;

    for (int kt = 0; kt < 32; kt++) {
        int buf = kt & 1;
        if (kt + 1 < 32) issue(kt + 1, buf ^ 1);
        CP_COMMIT();
        CP_WAIT1();
        __syncthreads();
        const float* Pf = Ps + buf*PV_PSZ;
        const float* Vf = Vs + buf*PV_VSZ;

        // side-channel: p = u * (1/L), streaming store only
        #pragma unroll
        for (int i = 0; i < 8; i++) {
            int v = tid + i*256;
            int r = v >> 4, c = (v & 15)*4;
            float4 s = *(const float4*)&Pf[r*PV_PP + c];
            float il = sl[r];
            stcs4(pb + (size_t)r*NS + kt*64 + c,
                  make_float4(s.x*il, s.y*il, s.z*il, s.w*il));
        }

        // single MMA: U~ x V~ (both already tf32 bit patterns)
        #pragma unroll
        for (int ks = 0; ks < 8; ks++) {
            int kk = ks * 8;
            uint32_t af[2][4], bf[4][2];
            #pragma unroll
            for (int i = 0; i < 2; i++) {
                int o = (wq + i*16 + (t >> 2))*PV_PP + kk + (t & 3);
                af[i][0] = __float_as_uint(Pf[o]);
                af[i][1] = __float_as_uint(Pf[o + 8*PV_PP]);
                af[i][2] = __float_as_uint(Pf[o + 4]);
                af[i][3] = __float_as_uint(Pf[o + 8*PV_PP + 4]);
            }
            #pragma unroll
            for (int j = 0; j < 4; j++) {
                int o = (kk + (t & 3))*PV_VP + wd + j*8 + (t >> 2);
                bf[j][0] = __float_as_uint(Vf[o]);
                bf[j][1] = __float_as_uint(Vf[o + 4*PV_VP]);
            }
            #pragma unroll
            for (int i = 0; i < 2; i++)
                #pragma unroll
                for (int j = 0; j < 4; j++)
                    mma_tf32(acc[i][j], af[i], bf[j]);
        }
        __syncthreads();
    }

    // epilogue: X = acc / L
    #pragma unroll
    for (int i = 0; i < 2; i++) {
        int lr = wq + i*16 + (t >> 2);
        float il0 = sl[lr], il1 = sl[lr + 8];
        int row = qt*128 + lr;
        #pragma unroll
        for (int j = 0; j < 4; j++) {
            int col = head*NDK + wd + j*8 + (t & 3)*2;
            *(float2*)&g_X[(size_t)(b*NS + row)*NDM + col] =
                make_float2(acc[i][j][0]*il0, acc[i][j][1]*il0);
            *(float2*)&g_X[(size_t)(b*NS + row + 8)*NDM + col] =
                make_float2(acc[i][j][2]*il1, acc[i][j][3]*il1);
        }
    }
}

// ---------------------------------------------------------------------------
extern "C" void kernel_launch(void* const* d_in, const int* in_sizes, int n_in,
                              void* d_out, int out_size)
{
    const float* query = (const float*)d_in[0];
    const float* key_i = (const float*)d_in[1];
    const float* value = (const float*)d_in[2];
    const float* qW = (const float*)d_in[3];
    const float* qb = (const float*)d_in[4];
    const float* kW = (const float*)d_in[5];
    const float* kb = (const float*)d_in[6];
    const float* vW = (const float*)d_in[7];
    const float* vb = (const float*)d_in[8];
    const float* oW = (const float*)d_in[9];
    const float* ob = (const float*)d_in[10];

    float* out   = (float*)d_out;                    // [B,S,D_MODEL]
    float* pattn = out + (size_t)NB * NS * NDM;      // [B,H,S,S]

    float *pQ, *pK, *pV, *pX;
    cudaGetSymbolAddress((void**)&pQ, g_Q);
    cudaGetSymbolAddress((void**)&pK, g_K);
    cudaGetSymbolAddress((void**)&pV, g_V);
    cudaGetSymbolAddress((void**)&pX, g_X);

    cudaFuncSetAttribute(attn_scores_mma,
                         cudaFuncAttributeMaxDynamicSharedMemorySize, SC_SMEM);
    cudaFuncSetAttribute(attn_pv_mma,
                         cudaFuncAttributeMaxDynamicSharedMemorySize, PV_SMEM);

    dim3 gG(NDM/128, NROWS/128);     // (8, 32)
    dim3 gKV(NROWS/64, 2);           // (64, 2) — K and V in one launch
    dim3 gA(NS/128, NH, NB);         // (16, 16, 2)

    // 1) Q projection (1xTF32), d-permuted + tf32-rounded output
    proj_mma<1><<<gG, 256>>>(query, qW, qb, pQ, NROWS, NDM, NDM);
    // 2) K + V projections merged (2xTF32), tf32-rounded outputs
    kvproj_mma<<<gKV, 256>>>(key_i, value, kW, kb, vW, vb, pK, pV, NROWS, NDM);
    // 3) u = tf32(exp(scores)) + row sums
    attn_scores_mma<<<gA, 256, SC_SMEM>>>(pattn);
    // 4) X = (U @ V)/L (single MMA), p = u/L streamed out
    attn_pv_mma<<<gA, 256, PV_SMEM>>>(pattn);
    // 5) output projection (1xTF32)
    proj_mma<0><<<gG, 256>>>(pX, oW, ob, out, NROWS, NDM, NDM);
}